// round 2
// baseline (speedup 1.0000x reference)
#include <cuda_runtime.h>
#include <math.h>

#define NWIN   63
#define NB     32
#define ND     1024
#define NBASIS 256
#define LAMC   0.2f
#define LRC    0.001f
#define B1C    0.9f
#define B2C    0.999f
#define EPSC   1e-8f
#define TOLC   1e-3f

// scratch (allowed: __device__ globals, no runtime alloc)
__device__ float g_xbuf[NWIN * NB * ND];     // normalized windows, 8.25 MB
__device__ float g_bsT[NBASIS * ND];         // basis transposed [k][j], 1 MB

// ---------------------------------------------------------------------------
// Prep 1: build normalized windows. grid (32 b, 63 win), 256 threads.
// x[w][b][f*8+t] = spec[b][f][w*4+t], then per-row (over 1024) min/max norm.
// ---------------------------------------------------------------------------
__global__ void prep_windows(const float* __restrict__ spec) {
    int b = blockIdx.x, wn = blockIdx.y;
    int t = threadIdx.x;

    float v[4];
    float mn = 3.402823466e38f, mx = -3.402823466e38f;
#pragma unroll
    for (int r = 0; r < 4; r++) {
        int idx = t + 256 * r;          // feature index f*8+tt
        int f = idx >> 3, tt = idx & 7;
        float val = spec[(b * 128 + f) * 256 + wn * 4 + tt];
        v[r] = val;
        mn = fminf(mn, val);
        mx = fmaxf(mx, val);
    }
#pragma unroll
    for (int o = 16; o > 0; o >>= 1) {
        mn = fminf(mn, __shfl_xor_sync(0xffffffffu, mn, o));
        mx = fmaxf(mx, __shfl_xor_sync(0xffffffffu, mx, o));
    }
    __shared__ float smn[8], smx[8];
    if ((t & 31) == 0) { smn[t >> 5] = mn; smx[t >> 5] = mx; }
    __syncthreads();
    float bmn = smn[0], bmx = smx[0];
#pragma unroll
    for (int i = 1; i < 8; i++) { bmn = fminf(bmn, smn[i]); bmx = fmaxf(bmx, smx[i]); }
    float d = bmx - bmn;

    float* dst = g_xbuf + (wn * NB + b) * ND;
#pragma unroll
    for (int r = 0; r < 4; r++)
        dst[t + 256 * r] = (v[r] - bmn) / d;
}

// ---------------------------------------------------------------------------
// Prep 2: transpose basis [1024,256] -> bsT [256,1024]. grid (32,8), blk (32,32)
// ---------------------------------------------------------------------------
__global__ void prep_bsT(const float* __restrict__ basis) {
    __shared__ float tile[32][33];
    int jb = blockIdx.x * 32, kb = blockIdx.y * 32;
    int tx = threadIdx.x, ty = threadIdx.y;
    tile[ty][tx] = basis[(jb + ty) * NBASIS + kb + tx];
    __syncthreads();
    g_bsT[(kb + ty) * ND + jb + tx] = tile[tx][ty];
}

// ---------------------------------------------------------------------------
// Main solver: one CTA per window, 512 threads (16 warps).
// SMEM: resid[32][1024] | coef[32][256] | slab[32][256] | red[64]
// ---------------------------------------------------------------------------
#define SMEM_FLOATS (32768 + 8192 + 8192 + 64)

__global__ __launch_bounds__(512, 1)
void sc_solve(const float* __restrict__ basis,
              const int* __restrict__ n_iter_p,
              float* __restrict__ out) {
    extern __shared__ float smem[];
    float* sresid = smem;                   // 32*1024
    float* scoef  = smem + 32768;           // 32*256
    float* sB     = smem + 40960;           // 32*256 slab
    float* sred   = smem + 49152;           // 32 + 32

    const int win = blockIdx.x;
    const int tid = threadIdx.x;
    const int w = tid >> 5, l = tid & 31;
    const float* xw = g_xbuf + win * NB * ND;
    const int n_iter = n_iter_p[0];

    // GEMM1 mapping: warp -> (b-block of 4, j-half); lane -> 4 j-groups of 4
    const int b0    = (w >> 1) * 4;
    const int jbase = (w & 1) * 512 + l * 4;      // + q*128, q=0..3
    // GEMM2 / Adam mapping: warp -> (b-block of 8, k-quarter); lane -> 2 k
    const int b2_0 = (w & 3) * 8;
    const int kk0  = (w >> 2) * 64 + l * 2;

    // init coef = 0.5/256
    for (int i = tid; i < NB * NBASIS; i += 512) scoef[i] = 0.5f / 256.0f;

    float m[16], vv[16];
#pragma unroll
    for (int i = 0; i < 16; i++) { m[i] = 0.f; vv[i] = 0.f; }
    float b1t = 1.f, b2t = 1.f;
    float old_loss = 1e-10f;

    __syncthreads();

    for (int it = 0; it < n_iter; ++it) {
        // ================= GEMM1: pred = coef @ basis^T; resid -> SMEM ======
        float acc[4][16];
#pragma unroll
        for (int i = 0; i < 4; i++)
#pragma unroll
            for (int jj = 0; jj < 16; jj++) acc[i][jj] = 0.f;

        const float4* sc4 = (const float4*)scoef;
#pragma unroll 2
        for (int k4 = 0; k4 < 64; k4++) {
            float4 c[4];
#pragma unroll
            for (int i = 0; i < 4; i++) c[i] = sc4[(b0 + i) * 64 + k4];
#pragma unroll
            for (int q = 0; q < 4; q++) {
                const int jcol = jbase + q * 128;
                const float4* bp =
                    (const float4*)(g_bsT + (k4 * 4) * ND + jcol);
                float4 bv[4];
#pragma unroll
                for (int kk = 0; kk < 4; kk++) bv[kk] = bp[kk * 256]; // +1024 floats
#pragma unroll
                for (int i = 0; i < 4; i++) {
#pragma unroll
                    for (int kk = 0; kk < 4; kk++) {
                        float ck = (kk == 0) ? c[i].x : (kk == 1) ? c[i].y
                                 : (kk == 2) ? c[i].z : c[i].w;
                        acc[i][q * 4 + 0] = fmaf(ck, bv[kk].x, acc[i][q * 4 + 0]);
                        acc[i][q * 4 + 1] = fmaf(ck, bv[kk].y, acc[i][q * 4 + 1]);
                        acc[i][q * 4 + 2] = fmaf(ck, bv[kk].z, acc[i][q * 4 + 2]);
                        acc[i][q * 4 + 3] = fmaf(ck, bv[kk].w, acc[i][q * 4 + 3]);
                    }
                }
            }
        }

        // resid = pred - x, mse partial, store resid
        float msep = 0.f;
#pragma unroll
        for (int i = 0; i < 4; i++) {
            const int b = b0 + i;
#pragma unroll
            for (int q = 0; q < 4; q++) {
                const int j = jbase + q * 128;
                float4 xv = *(const float4*)(xw + b * ND + j);
                float r0 = acc[i][q * 4 + 0] - xv.x;
                float r1 = acc[i][q * 4 + 1] - xv.y;
                float r2 = acc[i][q * 4 + 2] - xv.z;
                float r3 = acc[i][q * 4 + 3] - xv.w;
                msep = fmaf(r0, r0, msep);
                msep = fmaf(r1, r1, msep);
                msep = fmaf(r2, r2, msep);
                msep = fmaf(r3, r3, msep);
                *(float4*)(sresid + b * ND + j) = make_float4(r0, r1, r2, r3);
            }
        }

        // L1 partial over a strided 16-chunk of current coef
        float l1p = 0.f;
        {
            const float4* p = (const float4*)scoef + tid * 4;
#pragma unroll
            for (int r = 0; r < 4; r++) {
                float4 cv = p[r];
                l1p += fabsf(cv.x) + fabsf(cv.y) + fabsf(cv.z) + fabsf(cv.w);
            }
        }

        // block reduce (also barriers resid writes before GEMM2)
#pragma unroll
        for (int o = 16; o > 0; o >>= 1) {
            msep += __shfl_xor_sync(0xffffffffu, msep, o);
            l1p  += __shfl_xor_sync(0xffffffffu, l1p, o);
        }
        if (l == 0) { sred[w] = msep; sred[16 + w] = l1p; }
        __syncthreads();
        float mse_sum = 0.f, l1_sum = 0.f;
#pragma unroll
        for (int i = 0; i < 16; i++) { mse_sum += sred[i]; l1_sum += sred[16 + i]; }
        const float loss = mse_sum * (1.0f / 32768.0f)
                         + LAMC * (l1_sum * (1.0f / 8192.0f));

        // ================= GEMM2: g = resid @ basis (slab-staged) ===========
        float g[16];
#pragma unroll
        for (int i = 0; i < 16; i++) g[i] = 0.f;

        for (int js = 0; js < ND; js += 32) {
            __syncthreads();   // previous slab consumed
            {
                const float4* src = (const float4*)(basis + js * NBASIS);
                float4* dstv = (float4*)sB;
#pragma unroll
                for (int r = 0; r < 4; r++)
                    dstv[tid + 512 * r] = src[tid + 512 * r];
            }
            __syncthreads();
#pragma unroll
            for (int j4 = 0; j4 < 32; j4 += 4) {
                float2 bk[4];
#pragma unroll
                for (int jj = 0; jj < 4; jj++)
                    bk[jj] = *(const float2*)(sB + (j4 + jj) * NBASIS + kk0);
#pragma unroll
                for (int i = 0; i < 8; i++) {
                    float4 r4 = *(const float4*)(sresid + (b2_0 + i) * ND + js + j4);
                    g[i * 2 + 0] = fmaf(r4.x, bk[0].x, g[i * 2 + 0]);
                    g[i * 2 + 0] = fmaf(r4.y, bk[1].x, g[i * 2 + 0]);
                    g[i * 2 + 0] = fmaf(r4.z, bk[2].x, g[i * 2 + 0]);
                    g[i * 2 + 0] = fmaf(r4.w, bk[3].x, g[i * 2 + 0]);
                    g[i * 2 + 1] = fmaf(r4.x, bk[0].y, g[i * 2 + 1]);
                    g[i * 2 + 1] = fmaf(r4.y, bk[1].y, g[i * 2 + 1]);
                    g[i * 2 + 1] = fmaf(r4.z, bk[2].y, g[i * 2 + 1]);
                    g[i * 2 + 1] = fmaf(r4.w, bk[3].y, g[i * 2 + 1]);
                }
            }
        }

        // ================= Adam update on owned 16 coefficients =============
        b1t *= B1C;
        b2t *= B2C;
        const float gs = 2.0f / 32768.0f;
#pragma unroll
        for (int i = 0; i < 8; i++) {
#pragma unroll
            for (int kk = 0; kk < 2; kk++) {
                const int idx = (b2_0 + i) * NBASIS + kk0 + kk;
                const int r = i * 2 + kk;
                float c = scoef[idx];
                float sg = (c > 0.f) ? 1.f : ((c < 0.f) ? -1.f : 0.f);
                float grad = g[r] * gs + (LAMC / 8192.0f) * sg;
                m[r]  = B1C * m[r] + (1.0f - B1C) * grad;
                vv[r] = B2C * vv[r] + (1.0f - B2C) * grad * grad;
                float mhat = m[r] / (1.0f - b1t);
                float vhat = vv[r] / (1.0f - b2t);
                c = c - LRC * mhat / (sqrtf(vhat) + EPSC);
                scoef[idx] = c;
            }
        }
        __syncthreads();   // coef visible for next GEMM1 / final store

        // convergence (AFTER update, matching lax.scan semantics)
        const float conv_m = fabsf(old_loss - loss) / old_loss;
        old_loss = loss;
        if (conv_m < TOLC) break;   // uniform across the block
    }

    // ================= output: out[b][k][win] ===============================
#pragma unroll
    for (int i = 0; i < 8; i++) {
        const int b = b2_0 + i;
#pragma unroll
        for (int kk = 0; kk < 2; kk++) {
            const int k = kk0 + kk;
            out[(b * NBASIS + k) * NWIN + win] = scoef[b * NBASIS + k];
        }
    }
}

// ---------------------------------------------------------------------------
extern "C" void kernel_launch(void* const* d_in, const int* in_sizes, int n_in,
                              void* d_out, int out_size) {
    const float* spec  = (const float*)d_in[0];
    const float* basis = (const float*)d_in[1];
    const int* n_iter  = (const int*)d_in[2];
    float* out = (float*)d_out;

    prep_windows<<<dim3(NB, NWIN), 256>>>(spec);
    prep_bsT<<<dim3(32, 8), dim3(32, 32)>>>(basis);

    size_t smem_bytes = SMEM_FLOATS * sizeof(float);   // ~192.3 KB
    cudaFuncSetAttribute(sc_solve, cudaFuncAttributeMaxDynamicSharedMemorySize,
                         (int)smem_bytes);
    sc_solve<<<NWIN, 512, smem_bytes>>>(basis, n_iter, out);
}

// round 5
// speedup vs baseline: 5.9778x; 5.9778x over previous
#include <cuda_runtime.h>
#include <math.h>

#define NWIN   63
#define NB     32
#define ND     1024
#define NBASIS 256
#define LAMC   0.2f
#define LRC    0.001f
#define B1C    0.9f
#define B2C    0.999f
#define EPSC   1e-8f
#define TOLC   1e-3f

// scratch (allowed: __device__ globals, no runtime alloc)
__device__ float g_xbuf[NWIN * NB * ND];      // normalized windows, 8.25 MB
__device__ float g_G[NBASIS * NBASIS];        // Gram matrix basis^T @ basis, 256 KB

// ---------------------------------------------------------------------------
// Prep 1: build normalized windows. grid (32 b, 63 win), 256 threads.
// x[w][b][f*8+t] = spec[b][f][w*4+t], per-(w,b)-row min/max normalize over 1024.
// ---------------------------------------------------------------------------
__global__ void prep_windows(const float* __restrict__ spec) {
    int b = blockIdx.x, wn = blockIdx.y;
    int t = threadIdx.x;

    float v[4];
    float mn = 3.402823466e38f, mx = -3.402823466e38f;
#pragma unroll
    for (int r = 0; r < 4; r++) {
        int idx = t + 256 * r;
        int f = idx >> 3, tt = idx & 7;
        float val = spec[(b * 128 + f) * 256 + wn * 4 + tt];
        v[r] = val;
        mn = fminf(mn, val);
        mx = fmaxf(mx, val);
    }
#pragma unroll
    for (int o = 16; o > 0; o >>= 1) {
        mn = fminf(mn, __shfl_xor_sync(0xffffffffu, mn, o));
        mx = fmaxf(mx, __shfl_xor_sync(0xffffffffu, mx, o));
    }
    __shared__ float smn[8], smx[8];
    if ((t & 31) == 0) { smn[t >> 5] = mn; smx[t >> 5] = mx; }
    __syncthreads();
    float bmn = smn[0], bmx = smx[0];
#pragma unroll
    for (int i = 1; i < 8; i++) { bmn = fminf(bmn, smn[i]); bmx = fmaxf(bmx, smx[i]); }
    float d = bmx - bmn;

    float* dst = g_xbuf + (wn * NB + b) * ND;
#pragma unroll
    for (int r = 0; r < 4; r++)
        dst[t + 256 * r] = (v[r] - bmn) / d;
}

// ---------------------------------------------------------------------------
// Prep 2: G = basis^T @ basis.  grid (8,8), 256 threads; 32x32 output tile.
// ---------------------------------------------------------------------------
__global__ void prep_G(const float* __restrict__ basis) {
    __shared__ float A[32][33], Bs[32][33];
    int k1b = blockIdx.y * 32, k2b = blockIdx.x * 32;
    int tx = threadIdx.x & 31, ty = threadIdx.x >> 5;   // 32 x 8
    float acc[4] = {0.f, 0.f, 0.f, 0.f};
    for (int j0 = 0; j0 < ND; j0 += 32) {
        __syncthreads();
#pragma unroll
        for (int s = 0; s < 4; s++) {
            A[ty + 8 * s][tx]  = basis[(j0 + ty + 8 * s) * NBASIS + k1b + tx];
            Bs[ty + 8 * s][tx] = basis[(j0 + ty + 8 * s) * NBASIS + k2b + tx];
        }
        __syncthreads();
#pragma unroll
        for (int jj = 0; jj < 32; jj++) {
            float bv = Bs[jj][tx];
            acc[0] = fmaf(A[jj][ty],      bv, acc[0]);
            acc[1] = fmaf(A[jj][ty + 8],  bv, acc[1]);
            acc[2] = fmaf(A[jj][ty + 16], bv, acc[2]);
            acc[3] = fmaf(A[jj][ty + 24], bv, acc[3]);
        }
    }
#pragma unroll
    for (int s = 0; s < 4; s++)
        g_G[(k1b + ty + 8 * s) * NBASIS + k2b + tx] = acc[s];
}

// ---------------------------------------------------------------------------
// Main solver: one CTA per window, 512 threads (16 warps).
// SMEM: coef[32][256] | h[32][256] | G-slab x2 [32][256] | x-slab x2 [32][32] | red
// Ownership (GEMM output == Adam == epilogue): warp w, lane l:
//   b0 = (w&7)*4  (4 rows),  k0 = (w>>3)*128 + l*4  (4 cols)
// ---------------------------------------------------------------------------
#define SMEM_FLOATS (8192 + 8192 + 2*8192 + 2*1024 + 64)

__global__ __launch_bounds__(512, 1)
void sc_solve(const float* __restrict__ basis,
              const int* __restrict__ n_iter_p,
              float* __restrict__ out) {
    extern __shared__ float smem[];
    float* scoef = smem;                 // 8192
    float* sh    = smem + 8192;          // 8192
    float* sG0   = smem + 16384;         // 2 x 8192
    float* sX0   = smem + 32768;         // 2 x 1024
    float* sred  = smem + 34816;         // 64

    const int win = blockIdx.x;
    const int tid = threadIdx.x;
    const int w = tid >> 5, l = tid & 31;
    const int b0 = (w & 7) * 4;
    const int k0 = (w >> 3) * 128 + l * 4;
    const float* xw = g_xbuf + win * NB * ND;
    const int n_iter = n_iter_p[0];

    // =================== Phase A: h = x @ basis, sumx2 ======================
    float hacc[4][4];
#pragma unroll
    for (int i = 0; i < 4; i++)
#pragma unroll
        for (int r = 0; r < 4; r++) hacc[i][r] = 0.f;
    float sx2 = 0.f;

    float4 pb[4], px;
    {   // preload slab 0 (basis rows 0..31, x cols 0..31)
        const float4* src = (const float4*)basis;
#pragma unroll
        for (int r = 0; r < 4; r++) pb[r] = src[tid + 512 * r];
        if (tid < 256) px = ((const float4*)xw)[(tid >> 3) * 256 + (tid & 7)];
        float4* d = (float4*)sG0;
#pragma unroll
        for (int r = 0; r < 4; r++) d[tid + 512 * r] = pb[r];
        if (tid < 256) ((float4*)sX0)[tid] = px;
    }

    for (int s = 0; s < 32; s++) {
        __syncthreads();
        const float* sB = sG0 + (s & 1) * 8192;
        const float* sx = sX0 + (s & 1) * 1024;
        if (s < 31) {
            const float4* src = (const float4*)(basis + (s + 1) * 32 * NBASIS);
#pragma unroll
            for (int r = 0; r < 4; r++) pb[r] = src[tid + 512 * r];
            if (tid < 256)
                px = ((const float4*)xw)[(tid >> 3) * 256 + (s + 1) * 8 + (tid & 7)];
        }
#pragma unroll
        for (int j4 = 0; j4 < 8; j4++) {
            float4 c[4];
#pragma unroll
            for (int i = 0; i < 4; i++)
                c[i] = ((const float4*)sx)[(b0 + i) * 8 + j4];
            float4 bv[4];
#pragma unroll
            for (int r = 0; r < 4; r++)
                bv[r] = *(const float4*)(sB + (j4 * 4 + r) * NBASIS + k0);
#pragma unroll
            for (int i = 0; i < 4; i++) {
                hacc[i][0] = fmaf(c[i].x, bv[0].x, hacc[i][0]);
                hacc[i][1] = fmaf(c[i].x, bv[0].y, hacc[i][1]);
                hacc[i][2] = fmaf(c[i].x, bv[0].z, hacc[i][2]);
                hacc[i][3] = fmaf(c[i].x, bv[0].w, hacc[i][3]);
                hacc[i][0] = fmaf(c[i].y, bv[1].x, hacc[i][0]);
                hacc[i][1] = fmaf(c[i].y, bv[1].y, hacc[i][1]);
                hacc[i][2] = fmaf(c[i].y, bv[1].z, hacc[i][2]);
                hacc[i][3] = fmaf(c[i].y, bv[1].w, hacc[i][3]);
                hacc[i][0] = fmaf(c[i].z, bv[2].x, hacc[i][0]);
                hacc[i][1] = fmaf(c[i].z, bv[2].y, hacc[i][1]);
                hacc[i][2] = fmaf(c[i].z, bv[2].z, hacc[i][2]);
                hacc[i][3] = fmaf(c[i].z, bv[2].w, hacc[i][3]);
                hacc[i][0] = fmaf(c[i].w, bv[3].x, hacc[i][0]);
                hacc[i][1] = fmaf(c[i].w, bv[3].y, hacc[i][1]);
                hacc[i][2] = fmaf(c[i].w, bv[3].z, hacc[i][2]);
                hacc[i][3] = fmaf(c[i].w, bv[3].w, hacc[i][3]);
                if (w < 8) {    // NOTE: lane-invariant values -> 32x overcount,
                    sx2 = fmaf(c[i].x, c[i].x, sx2);   // corrected by 1/32 below
                    sx2 = fmaf(c[i].y, c[i].y, sx2);
                    sx2 = fmaf(c[i].z, c[i].z, sx2);
                    sx2 = fmaf(c[i].w, c[i].w, sx2);
                }
            }
        }
        if (s < 31) {
            float4* d = (float4*)(sG0 + ((s + 1) & 1) * 8192);
#pragma unroll
            for (int r = 0; r < 4; r++) d[tid + 512 * r] = pb[r];
            if (tid < 256) ((float4*)(sX0 + ((s + 1) & 1) * 1024))[tid] = px;
        }
    }

    // write h, reduce sx2, init coef
#pragma unroll
    for (int i = 0; i < 4; i++)
        *(float4*)(sh + (b0 + i) * NBASIS + k0) =
            make_float4(hacc[i][0], hacc[i][1], hacc[i][2], hacc[i][3]);
#pragma unroll
    for (int o = 16; o > 0; o >>= 1)
        sx2 += __shfl_xor_sync(0xffffffffu, sx2, o);
    // BUGFIX (R3): every lane accumulated identical (broadcast) values, so the
    // 32-lane reduction overcounts by exactly 32x. 1/32 is a power of two ->
    // exact correction.
    if (l == 0 && w < 8) sred[w] = sx2 * (1.0f / 32.0f);
    for (int idx = tid; idx < NB * NBASIS; idx += 512) scoef[idx] = 0.5f / 256.0f;

    // pre-stage G slab 0 into buf0 (G slabs re-staged each iteration below)
    float4 pg[4];
    {
        const float4* src = (const float4*)g_G;
#pragma unroll
        for (int r = 0; r < 4; r++) pg[r] = src[tid + 512 * r];
        float4* d = (float4*)sG0;
#pragma unroll
        for (int r = 0; r < 4; r++) d[tid + 512 * r] = pg[r];
    }
    __syncthreads();
    float sumx2 = 0.f;
#pragma unroll
    for (int i = 0; i < 8; i++) sumx2 += sred[i];

    // =================== Phase B: Adam iterations ===========================
    float m[16], vv[16];
#pragma unroll
    for (int i = 0; i < 16; i++) { m[i] = 0.f; vv[i] = 0.f; }
    float b1t = 1.f, b2t = 1.f;
    float old_loss = 1e-10f;

    for (int it = 0; it < n_iter; ++it) {
        // ---- cg = coef @ G (double-buffered 32-row G slabs from L2) ----
        float cg[4][4];
#pragma unroll
        for (int i = 0; i < 4; i++)
#pragma unroll
            for (int r = 0; r < 4; r++) cg[i][r] = 0.f;

        const float4* sc4 = (const float4*)scoef;
        for (int s = 0; s < 8; s++) {
            __syncthreads();
            const float* sB = sG0 + (s & 1) * 8192;
            const int nxt = (s < 7) ? (s + 1) : 0;   // re-stage slab0 for next iter
            {
                const float4* src = (const float4*)(g_G + nxt * 32 * NBASIS);
#pragma unroll
                for (int r = 0; r < 4; r++) pg[r] = src[tid + 512 * r];
            }
#pragma unroll
            for (int kk4 = 0; kk4 < 8; kk4++) {
                float4 c[4];
#pragma unroll
                for (int i = 0; i < 4; i++)
                    c[i] = sc4[(b0 + i) * 64 + s * 8 + kk4];   // broadcast LDS
                float4 gv[4];
#pragma unroll
                for (int r = 0; r < 4; r++)
                    gv[r] = *(const float4*)(sB + (kk4 * 4 + r) * NBASIS + k0);
#pragma unroll
                for (int i = 0; i < 4; i++) {
                    cg[i][0] = fmaf(c[i].x, gv[0].x, cg[i][0]);
                    cg[i][1] = fmaf(c[i].x, gv[0].y, cg[i][1]);
                    cg[i][2] = fmaf(c[i].x, gv[0].z, cg[i][2]);
                    cg[i][3] = fmaf(c[i].x, gv[0].w, cg[i][3]);
                    cg[i][0] = fmaf(c[i].y, gv[1].x, cg[i][0]);
                    cg[i][1] = fmaf(c[i].y, gv[1].y, cg[i][1]);
                    cg[i][2] = fmaf(c[i].y, gv[1].z, cg[i][2]);
                    cg[i][3] = fmaf(c[i].y, gv[1].w, cg[i][3]);
                    cg[i][0] = fmaf(c[i].z, gv[2].x, cg[i][0]);
                    cg[i][1] = fmaf(c[i].z, gv[2].y, cg[i][1]);
                    cg[i][2] = fmaf(c[i].z, gv[2].z, cg[i][2]);
                    cg[i][3] = fmaf(c[i].z, gv[2].w, cg[i][3]);
                    cg[i][0] = fmaf(c[i].w, gv[3].x, cg[i][0]);
                    cg[i][1] = fmaf(c[i].w, gv[3].y, cg[i][1]);
                    cg[i][2] = fmaf(c[i].w, gv[3].z, cg[i][2]);
                    cg[i][3] = fmaf(c[i].w, gv[3].w, cg[i][3]);
                }
            }
            {   // stage next slab (buf is free: its last readers passed this s's sync)
                float4* d = (float4*)(sG0 + ((s + 1) & 1) * 8192);
#pragma unroll
                for (int r = 0; r < 4; r++) d[tid + 512 * r] = pg[r];
            }
        }

        // ---- loss partials over owned 16 elements (disjoint across threads) ----
        float pcg = 0.f, pch = 0.f, pl1 = 0.f;
#pragma unroll
        for (int i = 0; i < 4; i++) {
            float4 cv = *(const float4*)(scoef + (b0 + i) * NBASIS + k0);
            float4 hv = *(const float4*)(sh + (b0 + i) * NBASIS + k0);
            pcg = fmaf(cg[i][0], cv.x, pcg);
            pcg = fmaf(cg[i][1], cv.y, pcg);
            pcg = fmaf(cg[i][2], cv.z, pcg);
            pcg = fmaf(cg[i][3], cv.w, pcg);
            pch = fmaf(cv.x, hv.x, pch);
            pch = fmaf(cv.y, hv.y, pch);
            pch = fmaf(cv.z, hv.z, pch);
            pch = fmaf(cv.w, hv.w, pch);
            pl1 += fabsf(cv.x) + fabsf(cv.y) + fabsf(cv.z) + fabsf(cv.w);
        }
#pragma unroll
        for (int o = 16; o > 0; o >>= 1) {
            pcg += __shfl_xor_sync(0xffffffffu, pcg, o);
            pch += __shfl_xor_sync(0xffffffffu, pch, o);
            pl1 += __shfl_xor_sync(0xffffffffu, pl1, o);
        }
        if (l == 0) { sred[w] = pcg; sred[16 + w] = pch; sred[32 + w] = pl1; }
        __syncthreads();      // also: all GEMM coef reads done before Adam writes
        float Scg = 0.f, Sch = 0.f, Sl1 = 0.f;
#pragma unroll
        for (int i = 0; i < 16; i++) {
            Scg += sred[i]; Sch += sred[16 + i]; Sl1 += sred[32 + i];
        }
        const float mse  = (Scg - 2.0f * Sch + sumx2) * (1.0f / 32768.0f);
        const float loss = mse + LAMC * (Sl1 * (1.0f / 8192.0f));

        // ---- Adam update on owned 16 coefficients ----
        b1t *= B1C;
        b2t *= B2C;
        const float gs = 2.0f / 32768.0f;
#pragma unroll
        for (int i = 0; i < 4; i++) {
#pragma unroll
            for (int r = 0; r < 4; r++) {
                const int idx = (b0 + i) * NBASIS + k0 + r;
                const int q = i * 4 + r;
                float c = scoef[idx];
                float hvv = sh[idx];
                float sg = (c > 0.f) ? 1.f : ((c < 0.f) ? -1.f : 0.f);
                float grad = (cg[i][r] - hvv) * gs + (LAMC / 8192.0f) * sg;
                m[q]  = B1C * m[q] + (1.0f - B1C) * grad;
                vv[q] = B2C * vv[q] + (1.0f - B2C) * grad * grad;
                float mhat = m[q] / (1.0f - b1t);
                float vhat = vv[q] / (1.0f - b2t);
                scoef[idx] = c - LRC * mhat / (sqrtf(vhat) + EPSC);
            }
        }
        // convergence AFTER update (lax.scan semantics); uniform across block
        const float conv_m = fabsf(old_loss - loss) / old_loss;
        old_loss = loss;
        if (conv_m < TOLC) break;
        // next iteration's s=0 __syncthreads publishes coef + slab0
    }

    // =================== output: out[b][k][win] =============================
#pragma unroll
    for (int i = 0; i < 4; i++)
#pragma unroll
        for (int r = 0; r < 4; r++) {
            const int b = b0 + i, k = k0 + r;
            out[(b * NBASIS + k) * NWIN + win] = scoef[b * NBASIS + k];
        }
}

// ---------------------------------------------------------------------------
extern "C" void kernel_launch(void* const* d_in, const int* in_sizes, int n_in,
                              void* d_out, int out_size) {
    const float* spec  = (const float*)d_in[0];
    const float* basis = (const float*)d_in[1];
    const int* n_iter  = (const int*)d_in[2];
    float* out = (float*)d_out;

    prep_windows<<<dim3(NB, NWIN), 256>>>(spec);
    prep_G<<<dim3(8, 8), 256>>>(basis);

    size_t smem_bytes = SMEM_FLOATS * sizeof(float);   // ~139.5 KB
    cudaFuncSetAttribute(sc_solve, cudaFuncAttributeMaxDynamicSharedMemorySize,
                         (int)smem_bytes);
    sc_solve<<<NWIN, 512, smem_bytes>>>(basis, n_iter, out);
}

// round 13
// speedup vs baseline: 9.4684x; 1.5839x over previous
#include <cuda_runtime.h>
#include <stdint.h>
#include <math.h>

#define NWIN   63
#define NB     32
#define ND     1024
#define NBASIS 256
#define KHALF  128
#define LAMC   0.2f
#define LRC    0.001f
#define B1C    0.9f
#define B2C    0.999f
#define EPSC   1e-8f
#define TOLC   1e-3f
#define C0     (0.5f / 256.0f)

// scratch (allowed: __device__ globals, no runtime alloc)
__device__ float g_xbuf[NWIN * NB * ND];      // normalized windows, 8.25 MB
__device__ float g_G[NBASIS * NBASIS];        // Gram matrix basis^T @ basis, 256 KB

// ---------------------------------------------------------------------------
// SMEM layout (floats) for sc_solve
// ---------------------------------------------------------------------------
#define SG_OFF     0          // G half [256][128]            = 32768
#define COEFO_OFF  32768      // own coef half [32][128]      = 4096
#define COEFP_OFF  36864      // peer coef half x2 parity     = 8192
#define SH_OFF     45056      // h half [32][128]             = 4096
#define SRED_OFF   49152      // 48 warp partials
#define SEX_OFF    49200      // [parity][rank][4] cross-CTA  = 16
#define SMEM_FLOATS 49216     // 196864 bytes

// ---------------------------------------------------------------------------
// Prep 1: build normalized windows. grid (32 b, 63 win), 256 threads.
// ---------------------------------------------------------------------------
__global__ void prep_windows(const float* __restrict__ spec) {
    int b = blockIdx.x, wn = blockIdx.y;
    int t = threadIdx.x;

    float v[4];
    float mn = 3.402823466e38f, mx = -3.402823466e38f;
#pragma unroll
    for (int r = 0; r < 4; r++) {
        int idx = t + 256 * r;
        int f = idx >> 3, tt = idx & 7;
        float val = spec[(b * 128 + f) * 256 + wn * 4 + tt];
        v[r] = val;
        mn = fminf(mn, val);
        mx = fmaxf(mx, val);
    }
#pragma unroll
    for (int o = 16; o > 0; o >>= 1) {
        mn = fminf(mn, __shfl_xor_sync(0xffffffffu, mn, o));
        mx = fmaxf(mx, __shfl_xor_sync(0xffffffffu, mx, o));
    }
    __shared__ float smn[8], smx[8];
    if ((t & 31) == 0) { smn[t >> 5] = mn; smx[t >> 5] = mx; }
    __syncthreads();
    float bmn = smn[0], bmx = smx[0];
#pragma unroll
    for (int i = 1; i < 8; i++) { bmn = fminf(bmn, smn[i]); bmx = fmaxf(bmx, smx[i]); }
    float d = bmx - bmn;

    float* dst = g_xbuf + (wn * NB + b) * ND;
#pragma unroll
    for (int r = 0; r < 4; r++)
        dst[t + 256 * r] = (v[r] - bmn) / d;
}

// ---------------------------------------------------------------------------
// Prep 2: G = basis^T @ basis.  grid (8,8), 256 threads; 32x32 output tile.
// ---------------------------------------------------------------------------
__global__ void prep_G(const float* __restrict__ basis) {
    __shared__ float A[32][33], Bs[32][33];
    int k1b = blockIdx.y * 32, k2b = blockIdx.x * 32;
    int tx = threadIdx.x & 31, ty = threadIdx.x >> 5;   // 32 x 8
    float acc[4] = {0.f, 0.f, 0.f, 0.f};
    for (int j0 = 0; j0 < ND; j0 += 32) {
        __syncthreads();
#pragma unroll
        for (int s = 0; s < 4; s++) {
            A[ty + 8 * s][tx]  = basis[(j0 + ty + 8 * s) * NBASIS + k1b + tx];
            Bs[ty + 8 * s][tx] = basis[(j0 + ty + 8 * s) * NBASIS + k2b + tx];
        }
        __syncthreads();
#pragma unroll
        for (int jj = 0; jj < 32; jj++) {
            float bv = Bs[jj][tx];
            acc[0] = fmaf(A[jj][ty],      bv, acc[0]);
            acc[1] = fmaf(A[jj][ty + 8],  bv, acc[1]);
            acc[2] = fmaf(A[jj][ty + 16], bv, acc[2]);
            acc[3] = fmaf(A[jj][ty + 24], bv, acc[3]);
        }
    }
#pragma unroll
    for (int s = 0; s < 4; s++)
        g_G[(k1b + ty + 8 * s) * NBASIS + k2b + tx] = acc[s];
}

// ---------------------------------------------------------------------------
// DSMEM helpers
// ---------------------------------------------------------------------------
__device__ __forceinline__ uint32_t smem_u32(const void* p) {
    uint32_t a;
    asm("{ .reg .u64 t; cvta.to.shared.u64 t, %1; cvt.u32.u64 %0, t; }"
        : "=r"(a) : "l"(p));
    return a;
}
__device__ __forceinline__ uint32_t mapa_peer(uint32_t laddr, int peer) {
    uint32_t r;
    asm("mapa.shared::cluster.u32 %0, %1, %2;" : "=r"(r) : "r"(laddr), "r"(peer));
    return r;
}
__device__ __forceinline__ void dst_v2(uint32_t raddr, float a, float b) {
    asm volatile("st.shared::cluster.v2.b32 [%0], {%1, %2};"
                 :: "r"(raddr), "r"(__float_as_uint(a)), "r"(__float_as_uint(b))
                 : "memory");
}
__device__ __forceinline__ void dst_b32(uint32_t raddr, float a) {
    asm volatile("st.shared::cluster.b32 [%0], %1;"
                 :: "r"(raddr), "r"(__float_as_uint(a)) : "memory");
}
__device__ __forceinline__ void cluster_sync() {
    asm volatile("barrier.cluster.arrive.aligned;" ::: "memory");
    asm volatile("barrier.cluster.wait.aligned;" ::: "memory");
}

// ---------------------------------------------------------------------------
// Main solver: 2-CTA cluster per window, 512 threads each. rank owns k-half.
// Thread map: warp w, lane l:  b0=(w&7)*4 (4 rows), k0l=(w>>3)*64+l*2 (2 cols)
// ---------------------------------------------------------------------------
__global__ __launch_bounds__(512, 1) __cluster_dims__(2, 1, 1)
void sc_solve(const float* __restrict__ basis,
              const int* __restrict__ n_iter_p,
              float* __restrict__ out) {
    extern __shared__ float smem[];
    float* sG    = smem + SG_OFF;
    float* coefO = smem + COEFO_OFF;
    float* coefP = smem + COEFP_OFF;
    float* sh    = smem + SH_OFF;
    float* sred  = smem + SRED_OFF;
    float* sex   = smem + SEX_OFF;

    const int win  = blockIdx.x >> 1;
    const int rank = blockIdx.x & 1;
    const int tid = threadIdx.x;
    const int w = tid >> 5, l = tid & 31;
    const int b0  = (w & 7) * 4;
    const int k0l = (w >> 3) * 64 + l * 2;
    const float* xw = g_xbuf + win * NB * ND;
    const int n_iter = n_iter_p[0];

    const uint32_t sbase = smem_u32(smem);
    const uint32_t rbase = mapa_peer(sbase, 1 - rank);

    // Phase A staging buffers live inside the sG region (G loaded afterwards)
    float* bslab = sG;           // 2 x 4096 (basis half-slab [32 j][128 k])
    float* xslab = sG + 8192;    // 2 x 1024 (x slab [32 b][32 j])

    // =================== Phase A: h(owned) = x @ basis[:,half], sumx2 =======
    float ha0[4], ha1[4];
#pragma unroll
    for (int i = 0; i < 4; i++) { ha0[i] = 0.f; ha1[i] = 0.f; }
    float sx2 = 0.f;

    float4 pb[2], px;
    {   // preload slab 0
        const float4* b4 = (const float4*)basis;
#pragma unroll
        for (int r = 0; r < 2; r++) {
            int i = tid + 512 * r;
            pb[r] = b4[(i >> 5) * 64 + rank * 32 + (i & 31)];
        }
        if (tid < 256) px = ((const float4*)xw)[(tid >> 3) * 256 + (tid & 7)];
        float4* d = (float4*)bslab;
#pragma unroll
        for (int r = 0; r < 2; r++) d[tid + 512 * r] = pb[r];
        if (tid < 256) ((float4*)xslab)[tid] = px;
    }

    for (int s = 0; s < 32; s++) {
        __syncthreads();
        const float* sb = bslab + (s & 1) * 4096;
        const float* sx = xslab + (s & 1) * 1024;
        if (s < 31) {
            const float4* b4 = (const float4*)basis;
#pragma unroll
            for (int r = 0; r < 2; r++) {
                int i = tid + 512 * r;
                pb[r] = b4[((s + 1) * 32 + (i >> 5)) * 64 + rank * 32 + (i & 31)];
            }
            if (tid < 256)
                px = ((const float4*)xw)[(tid >> 3) * 256 + (s + 1) * 8 + (tid & 7)];
        }
#pragma unroll
        for (int j4 = 0; j4 < 8; j4++) {
            float4 c[4];
#pragma unroll
            for (int i = 0; i < 4; i++)
                c[i] = ((const float4*)sx)[(b0 + i) * 8 + j4];
            float2 bv[4];
#pragma unroll
            for (int r = 0; r < 4; r++)
                bv[r] = *(const float2*)(sb + (j4 * 4 + r) * KHALF + k0l);
#pragma unroll
            for (int i = 0; i < 4; i++) {
                ha0[i] = fmaf(c[i].x, bv[0].x, ha0[i]);
                ha1[i] = fmaf(c[i].x, bv[0].y, ha1[i]);
                ha0[i] = fmaf(c[i].y, bv[1].x, ha0[i]);
                ha1[i] = fmaf(c[i].y, bv[1].y, ha1[i]);
                ha0[i] = fmaf(c[i].z, bv[2].x, ha0[i]);
                ha1[i] = fmaf(c[i].z, bv[2].y, ha1[i]);
                ha0[i] = fmaf(c[i].w, bv[3].x, ha0[i]);
                ha1[i] = fmaf(c[i].w, bv[3].y, ha1[i]);
                if (w < 8) {    // lane-invariant values -> 32x overcount, /32 below
                    sx2 = fmaf(c[i].x, c[i].x, sx2);
                    sx2 = fmaf(c[i].y, c[i].y, sx2);
                    sx2 = fmaf(c[i].z, c[i].z, sx2);
                    sx2 = fmaf(c[i].w, c[i].w, sx2);
                }
            }
        }
        if (s < 31) {
            float4* d = (float4*)(bslab + ((s + 1) & 1) * 4096);
#pragma unroll
            for (int r = 0; r < 2; r++) d[tid + 512 * r] = pb[r];
            if (tid < 256) ((float4*)(xslab + ((s + 1) & 1) * 1024))[tid] = px;
        }
    }

    // write h (owned half), reduce sx2
#pragma unroll
    for (int i = 0; i < 4; i++)
        *(float2*)(sh + (b0 + i) * KHALF + k0l) = make_float2(ha0[i], ha1[i]);
#pragma unroll
    for (int o = 16; o > 0; o >>= 1)
        sx2 += __shfl_xor_sync(0xffffffffu, sx2, o);
    if (l == 0 && w < 8) sred[w] = sx2 * (1.0f / 32.0f);   // exact /32 correction
    __syncthreads();   // staging buffers fully consumed; sred visible

    // load G half [256][128] into sG; init coef (own + peer-parity0 buffer)
    {
        const float4* G4 = (const float4*)g_G;
        float4* d = (float4*)sG;
#pragma unroll
        for (int r = 0; r < 16; r++) {
            int i = tid + 512 * r;
            d[i] = G4[(i >> 5) * 64 + rank * 32 + (i & 31)];
        }
    }
#pragma unroll
    for (int r = 0; r < 8; r++) coefO[tid + 512 * r] = C0;
#pragma unroll
    for (int r = 0; r < 8; r++) coefP[tid + 512 * r] = C0;   // parity-0 buffer
    float sumx2 = 0.f;
#pragma unroll
    for (int i = 0; i < 8; i++) sumx2 += sred[i];
    __syncthreads();

    // =================== Phase B: Adam iterations ===========================
    float m[8], vv[8];
#pragma unroll
    for (int i = 0; i < 8; i++) { m[i] = 0.f; vv[i] = 0.f; }
    float b1t = 1.f, b2t = 1.f;
    float old_loss = 1e-10f;

    for (int it = 0; it < n_iter; ++it) {
        const int p = it & 1;
        // half0 = coef cols [0,128), half1 = [128,256)
        const float4* h0 = (const float4*)((rank == 0) ? coefO : coefP + p * 4096);
        const float4* h1 = (const float4*)((rank == 0) ? coefP + p * 4096 : coefO);

        // ---- cg(owned) = coef(full) @ G[:, owned] (all SMEM-resident) ----
        float cg0[4], cg1[4];
#pragma unroll
        for (int i = 0; i < 4; i++) { cg0[i] = 0.f; cg1[i] = 0.f; }

#pragma unroll 8
        for (int s4 = 0; s4 < 32; s4++) {
            float4 c[4];
#pragma unroll
            for (int i = 0; i < 4; i++) c[i] = h0[(b0 + i) * 32 + s4];
            float2 gv[4];
#pragma unroll
            for (int r = 0; r < 4; r++)
                gv[r] = *(const float2*)(sG + (s4 * 4 + r) * KHALF + k0l);
#pragma unroll
            for (int i = 0; i < 4; i++) {
                cg0[i] = fmaf(c[i].x, gv[0].x, cg0[i]);
                cg1[i] = fmaf(c[i].x, gv[0].y, cg1[i]);
                cg0[i] = fmaf(c[i].y, gv[1].x, cg0[i]);
                cg1[i] = fmaf(c[i].y, gv[1].y, cg1[i]);
                cg0[i] = fmaf(c[i].z, gv[2].x, cg0[i]);
                cg1[i] = fmaf(c[i].z, gv[2].y, cg1[i]);
                cg0[i] = fmaf(c[i].w, gv[3].x, cg0[i]);
                cg1[i] = fmaf(c[i].w, gv[3].y, cg1[i]);
            }
        }
#pragma unroll 8
        for (int s4 = 0; s4 < 32; s4++) {
            float4 c[4];
#pragma unroll
            for (int i = 0; i < 4; i++) c[i] = h1[(b0 + i) * 32 + s4];
            float2 gv[4];
#pragma unroll
            for (int r = 0; r < 4; r++)
                gv[r] = *(const float2*)(sG + (128 + s4 * 4 + r) * KHALF + k0l);
#pragma unroll
            for (int i = 0; i < 4; i++) {
                cg0[i] = fmaf(c[i].x, gv[0].x, cg0[i]);
                cg1[i] = fmaf(c[i].x, gv[0].y, cg1[i]);
                cg0[i] = fmaf(c[i].y, gv[1].x, cg0[i]);
                cg1[i] = fmaf(c[i].y, gv[1].y, cg1[i]);
                cg0[i] = fmaf(c[i].z, gv[2].x, cg0[i]);
                cg1[i] = fmaf(c[i].z, gv[2].y, cg1[i]);
                cg0[i] = fmaf(c[i].w, gv[3].x, cg0[i]);
                cg1[i] = fmaf(c[i].w, gv[3].y, cg1[i]);
            }
        }

        // ---- loss partials over owned 8 elements (pre-update coef) ----
        float pcg = 0.f, pch = 0.f, pl1 = 0.f;
        float cva[4][2], hva[4][2];
#pragma unroll
        for (int i = 0; i < 4; i++) {
            float2 cv = *(const float2*)(coefO + (b0 + i) * KHALF + k0l);
            float2 hv = *(const float2*)(sh + (b0 + i) * KHALF + k0l);
            cva[i][0] = cv.x; cva[i][1] = cv.y;
            hva[i][0] = hv.x; hva[i][1] = hv.y;
            pcg = fmaf(cg0[i], cv.x, pcg);
            pcg = fmaf(cg1[i], cv.y, pcg);
            pch = fmaf(cv.x, hv.x, pch);
            pch = fmaf(cv.y, hv.y, pch);
            pl1 += fabsf(cv.x) + fabsf(cv.y);
        }
#pragma unroll
        for (int o = 16; o > 0; o >>= 1) {
            pcg += __shfl_xor_sync(0xffffffffu, pcg, o);
            pch += __shfl_xor_sync(0xffffffffu, pch, o);
            pl1 += __shfl_xor_sync(0xffffffffu, pl1, o);
        }
        if (l == 0) { sred[w] = pcg; sred[16 + w] = pch; sred[32 + w] = pl1; }
        __syncthreads();   // GEMM coef reads done; sred published

        if (tid == 0) {
            float a = 0.f, b = 0.f, c = 0.f;
#pragma unroll
            for (int i = 0; i < 16; i++) {
                a += sred[i]; b += sred[16 + i]; c += sred[32 + i];
            }
            const int slot = SEX_OFF + p * 8 + rank * 4;
            sex[p * 8 + rank * 4 + 0] = a;
            sex[p * 8 + rank * 4 + 1] = b;
            sex[p * 8 + rank * 4 + 2] = c;
            dst_b32(rbase + (slot + 0) * 4, a);
            dst_b32(rbase + (slot + 1) * 4, b);
            dst_b32(rbase + (slot + 2) * 4, c);
        }

        // ---- Adam update on owned 8 coefficients; push to peer (parity^1) --
        b1t *= B1C;
        b2t *= B2C;
        const float gs = 2.0f / 32768.0f;
        const float rb1 = 1.0f / (1.0f - b1t);
        const float rb2 = 1.0f / (1.0f - b2t);
#pragma unroll
        for (int i = 0; i < 4; i++) {
            const int idxl = (b0 + i) * KHALF + k0l;
            float nc[2];
#pragma unroll
            for (int kk = 0; kk < 2; kk++) {
                const int q = i * 2 + kk;
                float c = cva[i][kk];
                float cgv = (kk == 0) ? cg0[i] : cg1[i];
                float sg = (c > 0.f) ? 1.f : ((c < 0.f) ? -1.f : 0.f);
                float grad = (cgv - hva[i][kk]) * gs + (LAMC / 8192.0f) * sg;
                m[q]  = B1C * m[q] + (1.0f - B1C) * grad;
                vv[q] = B2C * vv[q] + (1.0f - B2C) * grad * grad;
                nc[kk] = c - LRC * (m[q] * rb1) / (sqrtf(vv[q] * rb2) + EPSC);
            }
            *(float2*)(coefO + idxl) = make_float2(nc[0], nc[1]);
            // peer's coefP buffer holds MY half at the same local offsets
            dst_v2(rbase + (COEFP_OFF + ((p ^ 1) * 4096) + idxl) * 4, nc[0], nc[1]);
        }

        cluster_sync();   // publishes coef half + loss partials to peer

        // ---- loss (identical on both ranks: fixed rank-order summation) ----
        const float Scg = sex[p * 8 + 0] + sex[p * 8 + 4];
        const float Sch = sex[p * 8 + 1] + sex[p * 8 + 5];
        const float Sl1 = sex[p * 8 + 2] + sex[p * 8 + 6];
        const float mse  = (Scg - 2.0f * Sch + sumx2) * (1.0f / 32768.0f);
        const float loss = mse + LAMC * (Sl1 * (1.0f / 8192.0f));

        const float conv_m = fabsf(old_loss - loss) / old_loss;
        old_loss = loss;
        if (conv_m < TOLC) break;   // uniform across cluster
    }

    // =================== output: out[b][k][win], owned half =================
#pragma unroll
    for (int i = 0; i < 4; i++) {
        const int b = b0 + i;
#pragma unroll
        for (int kk = 0; kk < 2; kk++) {
            const int kg = rank * KHALF + k0l + kk;
            out[(b * NBASIS + kg) * NWIN + win] = coefO[(b0 + i) * KHALF + k0l + kk];
        }
    }
}

// ---------------------------------------------------------------------------
extern "C" void kernel_launch(void* const* d_in, const int* in_sizes, int n_in,
                              void* d_out, int out_size) {
    const float* spec  = (const float*)d_in[0];
    const float* basis = (const float*)d_in[1];
    const int* n_iter  = (const int*)d_in[2];
    float* out = (float*)d_out;

    prep_windows<<<dim3(NB, NWIN), 256>>>(spec);
    prep_G<<<dim3(8, 8), 256>>>(basis);

    size_t smem_bytes = SMEM_FLOATS * sizeof(float);   // ~192.3 KB
    cudaFuncSetAttribute(sc_solve, cudaFuncAttributeMaxDynamicSharedMemorySize,
                         (int)smem_bytes);
    sc_solve<<<2 * NWIN, 512, smem_bytes>>>(basis, n_iter, out);
}

// round 15
// speedup vs baseline: 16.5384x; 1.7467x over previous
#include <cuda_runtime.h>
#include <cuda_bf16.h>
#include <stdint.h>
#include <math.h>

#define NWIN   63
#define NB     32
#define ND     1024
#define NBASIS 256
#define KHALF  128
#define LAMC   0.2f
#define LRC    0.001f
#define B1C    0.9f
#define B2C    0.999f
#define EPSC   1e-8f
#define TOLC   1e-3f
#define C0     (0.5f / 256.0f)

// scratch (allowed: __device__ globals, no runtime alloc)
__device__ float g_xbuf[NWIN * NB * ND];      // normalized windows, 8.25 MB
__device__ float g_G[NBASIS * NBASIS];        // Gram matrix basis^T @ basis

// ---------------- dynamic SMEM byte offsets --------------------------------
// Rows padded to 264 bf16 = 528 B so ldmatrix 8-row address sets are bank-clean.
#define ROWB    528
#define A_T(p,pl) ((p) * 33792 + (pl) * 16896)   // coef [32][256] bf16, parity x plane
#define B_T(pl)   (67584 + (pl) * 67584)         // G_own [128][256] bf16, plane
#define SH_B      67584                          // h fp32 [32][128] (overlaps B, pre-fill)
#define SRED_B    202752                         // 48 floats
#define SEX_B     202944                         // 16 floats
#define SMEM_BYTES 203264

// ---------------------------------------------------------------------------
// Prep 1: build normalized windows. grid (32 b, 63 win), 256 threads.
// ---------------------------------------------------------------------------
__global__ void prep_windows(const float* __restrict__ spec) {
    int b = blockIdx.x, wn = blockIdx.y;
    int t = threadIdx.x;

    float v[4];
    float mn = 3.402823466e38f, mx = -3.402823466e38f;
#pragma unroll
    for (int r = 0; r < 4; r++) {
        int idx = t + 256 * r;
        int f = idx >> 3, tt = idx & 7;
        float val = spec[(b * 128 + f) * 256 + wn * 4 + tt];
        v[r] = val;
        mn = fminf(mn, val);
        mx = fmaxf(mx, val);
    }
#pragma unroll
    for (int o = 16; o > 0; o >>= 1) {
        mn = fminf(mn, __shfl_xor_sync(0xffffffffu, mn, o));
        mx = fmaxf(mx, __shfl_xor_sync(0xffffffffu, mx, o));
    }
    __shared__ float smn[8], smx[8];
    if ((t & 31) == 0) { smn[t >> 5] = mn; smx[t >> 5] = mx; }
    __syncthreads();
    float bmn = smn[0], bmx = smx[0];
#pragma unroll
    for (int i = 1; i < 8; i++) { bmn = fminf(bmn, smn[i]); bmx = fmaxf(bmx, smx[i]); }
    float d = bmx - bmn;

    float* dst = g_xbuf + (wn * NB + b) * ND;
#pragma unroll
    for (int r = 0; r < 4; r++)
        dst[t + 256 * r] = (v[r] - bmn) / d;
}

// ---------------------------------------------------------------------------
// Prep 2: G = basis^T @ basis.  grid (8,8), 256 threads; 32x32 output tile.
// ---------------------------------------------------------------------------
__global__ void prep_G(const float* __restrict__ basis) {
    __shared__ float A[32][33], Bs[32][33];
    int k1b = blockIdx.y * 32, k2b = blockIdx.x * 32;
    int tx = threadIdx.x & 31, ty = threadIdx.x >> 5;
    float acc[4] = {0.f, 0.f, 0.f, 0.f};
    for (int j0 = 0; j0 < ND; j0 += 32) {
        __syncthreads();
#pragma unroll
        for (int s = 0; s < 4; s++) {
            A[ty + 8 * s][tx]  = basis[(j0 + ty + 8 * s) * NBASIS + k1b + tx];
            Bs[ty + 8 * s][tx] = basis[(j0 + ty + 8 * s) * NBASIS + k2b + tx];
        }
        __syncthreads();
#pragma unroll
        for (int jj = 0; jj < 32; jj++) {
            float bv = Bs[jj][tx];
            acc[0] = fmaf(A[jj][ty],      bv, acc[0]);
            acc[1] = fmaf(A[jj][ty + 8],  bv, acc[1]);
            acc[2] = fmaf(A[jj][ty + 16], bv, acc[2]);
            acc[3] = fmaf(A[jj][ty + 24], bv, acc[3]);
        }
    }
#pragma unroll
    for (int s = 0; s < 4; s++)
        g_G[(k1b + ty + 8 * s) * NBASIS + k2b + tx] = acc[s];
}

// ---------------------------------------------------------------------------
// helpers
// ---------------------------------------------------------------------------
__device__ __forceinline__ uint32_t smem_u32(const void* p) {
    uint32_t a;
    asm("{ .reg .u64 t; cvta.to.shared.u64 t, %1; cvt.u32.u64 %0, t; }"
        : "=r"(a) : "l"(p));
    return a;
}
__device__ __forceinline__ uint32_t mapa_peer(uint32_t laddr, int peer) {
    uint32_t r;
    asm("mapa.shared::cluster.u32 %0, %1, %2;" : "=r"(r) : "r"(laddr), "r"(peer));
    return r;
}
__device__ __forceinline__ void dst_f32(uint32_t raddr, float a) {
    asm volatile("st.shared::cluster.b32 [%0], %1;"
                 :: "r"(raddr), "r"(__float_as_uint(a)) : "memory");
}
__device__ __forceinline__ void dst_u32(uint32_t raddr, uint32_t a) {
    asm volatile("st.shared::cluster.b32 [%0], %1;"
                 :: "r"(raddr), "r"(a) : "memory");
}
__device__ __forceinline__ void cluster_sync() {
    asm volatile("barrier.cluster.arrive.aligned;" ::: "memory");
    asm volatile("barrier.cluster.wait.aligned;" ::: "memory");
}
__device__ __forceinline__ void ldsm4(uint32_t& r0, uint32_t& r1,
                                      uint32_t& r2, uint32_t& r3, uint32_t addr) {
    asm volatile("ldmatrix.sync.aligned.m8n8.x4.shared.b16 {%0,%1,%2,%3}, [%4];"
                 : "=r"(r0), "=r"(r1), "=r"(r2), "=r"(r3) : "r"(addr));
}
__device__ __forceinline__ void mma16816(float& c0, float& c1, float& c2, float& c3,
                                         uint32_t a0, uint32_t a1, uint32_t a2,
                                         uint32_t a3, uint32_t b0, uint32_t b1) {
    asm volatile(
        "mma.sync.aligned.m16n8k16.row.col.f32.bf16.bf16.f32 "
        "{%0,%1,%2,%3}, {%4,%5,%6,%7}, {%8,%9}, {%0,%1,%2,%3};"
        : "+f"(c0), "+f"(c1), "+f"(c2), "+f"(c3)
        : "r"(a0), "r"(a1), "r"(a2), "r"(a3), "r"(b0), "r"(b1));
}
__device__ __forceinline__ unsigned short bfraw(__nv_bfloat16 h) {
    return *reinterpret_cast<unsigned short*>(&h);
}

// ---------------------------------------------------------------------------
// Main solver: 2-CTA cluster per window, 512 threads. rank owns k-half.
// GEMM (per iter): cg[b=32][n=k_own 128] = coef[32][256] @ G_own^T via
// mma.sync m16n8k16 bf16 3-pass split. Warp w: mtile mb=(w&1)*16, ntile
// nb=(w>>1)*16; owns the m16xn16 output fragment (8 fp32/lane).
// ---------------------------------------------------------------------------
__global__ __launch_bounds__(512, 1) __cluster_dims__(2, 1, 1)
void sc_solve(const float* __restrict__ basis,
              const int* __restrict__ n_iter_p,
              float* __restrict__ out) {
    extern __shared__ float smem[];
    char* smem8 = (char*)smem;
    float* bslab = smem;                        // Phase A staging (A region)
    float* xslab = smem + 8192;
    float* shf   = (float*)(smem8 + SH_B);
    float* sredf = (float*)(smem8 + SRED_B);
    float* sexf  = (float*)(smem8 + SEX_B);

    const int win  = blockIdx.x >> 1;
    const int rank = blockIdx.x & 1;
    const int tid = threadIdx.x;
    const int w = tid >> 5, l = tid & 31;
    const float* xw = g_xbuf + win * NB * ND;
    const int n_iter = n_iter_p[0];

    const uint32_t sbase = smem_u32(smem);
    const uint32_t rbase = mapa_peer(sbase, 1 - rank);

    // =================== Phase A: h(owned) = x @ basis[:,half], sumx2 =======
    {
        const int b0  = (w & 7) * 4;
        const int k0l = (w >> 3) * 64 + l * 2;
        float ha0[4], ha1[4];
#pragma unroll
        for (int i = 0; i < 4; i++) { ha0[i] = 0.f; ha1[i] = 0.f; }
        float sx2 = 0.f;

        float4 pb[2], px;
        {
            const float4* b4 = (const float4*)basis;
#pragma unroll
            for (int r = 0; r < 2; r++) {
                int i = tid + 512 * r;
                pb[r] = b4[(i >> 5) * 64 + rank * 32 + (i & 31)];
            }
            if (tid < 256) px = ((const float4*)xw)[(tid >> 3) * 256 + (tid & 7)];
            float4* d = (float4*)bslab;
#pragma unroll
            for (int r = 0; r < 2; r++) d[tid + 512 * r] = pb[r];
            if (tid < 256) ((float4*)xslab)[tid] = px;
        }

        for (int s = 0; s < 32; s++) {
            __syncthreads();
            const float* sb = bslab + (s & 1) * 4096;
            const float* sx = xslab + (s & 1) * 1024;
            if (s < 31) {
                const float4* b4 = (const float4*)basis;
#pragma unroll
                for (int r = 0; r < 2; r++) {
                    int i = tid + 512 * r;
                    pb[r] = b4[((s + 1) * 32 + (i >> 5)) * 64 + rank * 32 + (i & 31)];
                }
                if (tid < 256)
                    px = ((const float4*)xw)[(tid >> 3) * 256 + (s + 1) * 8 + (tid & 7)];
            }
#pragma unroll
            for (int j4 = 0; j4 < 8; j4++) {
                float4 c[4];
#pragma unroll
                for (int i = 0; i < 4; i++)
                    c[i] = ((const float4*)sx)[(b0 + i) * 8 + j4];
                float2 bv[4];
#pragma unroll
                for (int r = 0; r < 4; r++)
                    bv[r] = *(const float2*)(sb + (j4 * 4 + r) * KHALF + k0l);
#pragma unroll
                for (int i = 0; i < 4; i++) {
                    ha0[i] = fmaf(c[i].x, bv[0].x, ha0[i]);
                    ha1[i] = fmaf(c[i].x, bv[0].y, ha1[i]);
                    ha0[i] = fmaf(c[i].y, bv[1].x, ha0[i]);
                    ha1[i] = fmaf(c[i].y, bv[1].y, ha1[i]);
                    ha0[i] = fmaf(c[i].z, bv[2].x, ha0[i]);
                    ha1[i] = fmaf(c[i].z, bv[2].y, ha1[i]);
                    ha0[i] = fmaf(c[i].w, bv[3].x, ha0[i]);
                    ha1[i] = fmaf(c[i].w, bv[3].y, ha1[i]);
                    if (w < 8) {    // lane-invariant -> exact /32 correction below
                        sx2 = fmaf(c[i].x, c[i].x, sx2);
                        sx2 = fmaf(c[i].y, c[i].y, sx2);
                        sx2 = fmaf(c[i].z, c[i].z, sx2);
                        sx2 = fmaf(c[i].w, c[i].w, sx2);
                    }
                }
            }
            if (s < 31) {
                float4* d = (float4*)(bslab + ((s + 1) & 1) * 4096);
#pragma unroll
                for (int r = 0; r < 2; r++) d[tid + 512 * r] = pb[r];
                if (tid < 256) ((float4*)(xslab + ((s + 1) & 1) * 1024))[tid] = px;
            }
        }

#pragma unroll
        for (int i = 0; i < 4; i++)
            *(float2*)(shf + (b0 + i) * KHALF + k0l) = make_float2(ha0[i], ha1[i]);
#pragma unroll
        for (int o = 16; o > 0; o >>= 1)
            sx2 += __shfl_xor_sync(0xffffffffu, sx2, o);
        if (l == 0 && w < 8) sredf[w] = sx2 * (1.0f / 32.0f);
    }
    __syncthreads();
    float sumx2 = 0.f;
#pragma unroll
    for (int i = 0; i < 8; i++) sumx2 += sredf[i];

    // =================== Phase B setup ======================================
    // fragment-mapped ownership
    const int mb = (w & 1) * 16;       // b tile base
    const int nb = (w >> 1) * 16;      // k_own tile base
    // ldmatrix lane addresses
    const uint32_t aoff = (uint32_t)(mb + (l & 15)) * ROWB + (uint32_t)((l >> 4) * 8) * 2;
    const uint32_t boff = (uint32_t)(nb + (l & 7) + (l >> 4) * 8) * ROWB
                        + (uint32_t)(((l >> 3) & 1) * 8) * 2;

    // owned elements: tile t, e in {0..3}: b = mb + (l>>2) + (e>>1)*8,
    //                 n = nb + t*8 + (l&3)*2 + (e&1)
    float coef[8], m[8], vv[8], hreg[8];
    uint32_t pairoff[4];   // byte offset of (b, kg_even) pair in A tiles
#pragma unroll
    for (int t = 0; t < 2; t++)
#pragma unroll
        for (int e = 0; e < 4; e++) {
            int b = mb + (l >> 2) + (e >> 1) * 8;
            int n = nb + t * 8 + (l & 3) * 2 + (e & 1);
            hreg[t * 4 + e] = shf[b * KHALF + n];
            coef[t * 4 + e] = C0;
            m[t * 4 + e] = 0.f; vv[t * 4 + e] = 0.f;
            if ((e & 1) == 0)
                pairoff[t * 2 + (e >> 1)] =
                    (uint32_t)b * ROWB + (uint32_t)(rank * KHALF + n) * 2;
        }
    __syncthreads();   // all h reads done before overwriting shf region (B fill)

    // fill B planes: B[pl][n][k] = bf16split(G[rank*128+n][k])  (static)
    for (int idx = tid; idx < 128 * 256; idx += 512) {
        int n = idx >> 8, k = idx & 255;
        float gv = g_G[(rank * KHALF + n) * NBASIS + k];
        __nv_bfloat16 hi = __float2bfloat16(gv);
        __nv_bfloat16 lo = __float2bfloat16(gv - __bfloat162float(hi));
        uint32_t o = (uint32_t)n * ROWB + (uint32_t)k * 2;
        *(__nv_bfloat16*)(smem8 + B_T(0) + o) = hi;
        *(__nv_bfloat16*)(smem8 + B_T(1) + o) = lo;
    }
    // fill A parity0: bf16 split of C0 everywhere [32][256]
    {
        __nv_bfloat16 hi0 = __float2bfloat16(C0);
        __nv_bfloat16 lo0 = __float2bfloat16(C0 - __bfloat162float(hi0));
        for (int idx = tid; idx < 32 * 256; idx += 512) {
            int b = idx >> 8, k = idx & 255;
            uint32_t o = (uint32_t)b * ROWB + (uint32_t)k * 2;
            *(__nv_bfloat16*)(smem8 + A_T(0, 0) + o) = hi0;
            *(__nv_bfloat16*)(smem8 + A_T(0, 1) + o) = lo0;
        }
    }
    __syncthreads();
    cluster_sync();

    float b1t = 1.f, b2t = 1.f;
    float old_loss = 1e-10f;

    const uint32_t bhiB = sbase + B_T(0) + boff;
    const uint32_t bloB = sbase + B_T(1) + boff;

    for (int it = 0; it < n_iter; ++it) {
        const int p = it & 1;
        const uint32_t ahiB = sbase + A_T(p, 0) + aoff;
        const uint32_t aloB = sbase + A_T(p, 1) + aoff;

        // ---- GEMM: 3-pass bf16-split, fp32 accum ----
        float c0[4] = {0.f, 0.f, 0.f, 0.f};   // tile0 (n = nb..nb+7)
        float c1[4] = {0.f, 0.f, 0.f, 0.f};   // tile1 (n = nb+8..nb+15)
#pragma unroll 4
        for (int kc = 0; kc < 16; kc++) {
            const uint32_t kb = (uint32_t)kc * 32;
            uint32_t ah0, ah1, ah2, ah3, al0, al1, al2, al3;
            uint32_t bh0, bh1, bh2, bh3, bl0, bl1, bl2, bl3;
            ldsm4(ah0, ah1, ah2, ah3, ahiB + kb);
            ldsm4(bh0, bh1, bh2, bh3, bhiB + kb);
            ldsm4(al0, al1, al2, al3, aloB + kb);
            ldsm4(bl0, bl1, bl2, bl3, bloB + kb);
            mma16816(c0[0], c0[1], c0[2], c0[3], ah0, ah1, ah2, ah3, bh0, bh1);
            mma16816(c1[0], c1[1], c1[2], c1[3], ah0, ah1, ah2, ah3, bh2, bh3);
            mma16816(c0[0], c0[1], c0[2], c0[3], ah0, ah1, ah2, ah3, bl0, bl1);
            mma16816(c1[0], c1[1], c1[2], c1[3], ah0, ah1, ah2, ah3, bl2, bl3);
            mma16816(c0[0], c0[1], c0[2], c0[3], al0, al1, al2, al3, bh0, bh1);
            mma16816(c1[0], c1[1], c1[2], c1[3], al0, al1, al2, al3, bh2, bh3);
        }
        float cg[8];
#pragma unroll
        for (int e = 0; e < 4; e++) { cg[e] = c0[e]; cg[4 + e] = c1[e]; }

        // ---- loss partials over owned 8 elements ----
        float pcg = 0.f, pch = 0.f, pl1 = 0.f;
#pragma unroll
        for (int i = 0; i < 8; i++) {
            pcg = fmaf(cg[i], coef[i], pcg);
            pch = fmaf(coef[i], hreg[i], pch);
            pl1 += fabsf(coef[i]);
        }
#pragma unroll
        for (int o = 16; o > 0; o >>= 1) {
            pcg += __shfl_xor_sync(0xffffffffu, pcg, o);
            pch += __shfl_xor_sync(0xffffffffu, pch, o);
            pl1 += __shfl_xor_sync(0xffffffffu, pl1, o);
        }
        if (l == 0) { sredf[w] = pcg; sredf[16 + w] = pch; sredf[32 + w] = pl1; }
        __syncthreads();   // GEMM A reads done; sred published

        if (tid == 0) {
            float a = 0.f, b = 0.f, c = 0.f;
#pragma unroll
            for (int i = 0; i < 16; i++) {
                a += sredf[i]; b += sredf[16 + i]; c += sredf[32 + i];
            }
            const int fo = p * 8 + rank * 4;
            sexf[fo + 0] = a; sexf[fo + 1] = b; sexf[fo + 2] = c;
            dst_f32(rbase + SEX_B + (fo + 0) * 4, a);
            dst_f32(rbase + SEX_B + (fo + 1) * 4, b);
            dst_f32(rbase + SEX_B + (fo + 2) * 4, c);
        }

        // ---- Adam on owned 8 ----
        b1t *= B1C;
        b2t *= B2C;
        const float gs = 2.0f / 32768.0f;
        const float rb1 = 1.0f / (1.0f - b1t);
        const float rb2 = 1.0f / (1.0f - b2t);
#pragma unroll
        for (int i = 0; i < 8; i++) {
            float c = coef[i];
            float sg = (c > 0.f) ? 1.f : ((c < 0.f) ? -1.f : 0.f);
            float grad = (cg[i] - hreg[i]) * gs + (LAMC / 8192.0f) * sg;
            m[i]  = B1C * m[i] + (1.0f - B1C) * grad;
            vv[i] = B2C * vv[i] + (1.0f - B2C) * grad * grad;
            coef[i] = c - LRC * (m[i] * rb1) / (sqrtf(vv[i] * rb2) + EPSC);
        }
        // write bf16 split pairs into A parity^1 (local + peer; adjacent k cols)
        const uint32_t lAh = A_T(p ^ 1, 0), lAl = A_T(p ^ 1, 1);
#pragma unroll
        for (int t = 0; t < 2; t++)
#pragma unroll
            for (int rs = 0; rs < 2; rs++) {
                const int i0 = t * 4 + rs * 2;
                __nv_bfloat16 h0 = __float2bfloat16(coef[i0]);
                __nv_bfloat16 h1 = __float2bfloat16(coef[i0 + 1]);
                __nv_bfloat16 l0 = __float2bfloat16(coef[i0] - __bfloat162float(h0));
                __nv_bfloat16 l1 = __float2bfloat16(coef[i0 + 1] - __bfloat162float(h1));
                uint32_t hp = (uint32_t)bfraw(h0) | ((uint32_t)bfraw(h1) << 16);
                uint32_t lp = (uint32_t)bfraw(l0) | ((uint32_t)bfraw(l1) << 16);
                const uint32_t o = pairoff[t * 2 + rs];
                *(uint32_t*)(smem8 + lAh + o) = hp;
                *(uint32_t*)(smem8 + lAl + o) = lp;
                dst_u32(rbase + lAh + o, hp);
                dst_u32(rbase + lAl + o, lp);
            }

        cluster_sync();   // publishes A parity^1 (both halves) + loss partials

        // ---- loss (identical on both ranks: fixed rank-order summation) ----
        const float Scg = sexf[p * 8 + 0] + sexf[p * 8 + 4];
        const float Sch = sexf[p * 8 + 1] + sexf[p * 8 + 5];
        const float Sl1 = sexf[p * 8 + 2] + sexf[p * 8 + 6];
        const float mse  = (Scg - 2.0f * Sch + sumx2) * (1.0f / 32768.0f);
        const float loss = mse + LAMC * (Sl1 * (1.0f / 8192.0f));

        const float conv_m = fabsf(old_loss - loss) / old_loss;
        old_loss = loss;
        if (conv_m < TOLC) break;   // uniform across cluster
    }

    // =================== output: out[b][kg][win] from registers =============
#pragma unroll
    for (int t = 0; t < 2; t++)
#pragma unroll
        for (int e = 0; e < 4; e++) {
            int b = mb + (l >> 2) + (e >> 1) * 8;
            int kg = rank * KHALF + nb + t * 8 + (l & 3) * 2 + (e & 1);
            out[(b * NBASIS + kg) * NWIN + win] = coef[t * 4 + e];
        }
}

// ---------------------------------------------------------------------------
extern "C" void kernel_launch(void* const* d_in, const int* in_sizes, int n_in,
                              void* d_out, int out_size) {
    const float* spec  = (const float*)d_in[0];
    const float* basis = (const float*)d_in[1];
    const int* n_iter  = (const int*)d_in[2];
    float* out = (float*)d_out;

    prep_windows<<<dim3(NB, NWIN), 256>>>(spec);
    prep_G<<<dim3(8, 8), 256>>>(basis);

    cudaFuncSetAttribute(sc_solve, cudaFuncAttributeMaxDynamicSharedMemorySize,
                         SMEM_BYTES);
    sc_solve<<<2 * NWIN, 512, SMEM_BYTES>>>(basis, n_iter, out);
}

// round 16
// speedup vs baseline: 19.0716x; 1.1532x over previous
#include <cuda_runtime.h>
#include <cuda_bf16.h>
#include <stdint.h>
#include <math.h>

#define NWIN   63
#define NB     32
#define ND     1024
#define NBASIS 256
#define KHALF  128
#define LAMC   0.2f
#define LRC    0.001f
#define B1C    0.9f
#define B2C    0.999f
#define EPSC   1e-8f
#define TOLC   1e-3f
#define C0     (0.5f / 256.0f)

// scratch (allowed: __device__ globals, no runtime alloc)
__device__ float g_G[NBASIS * NBASIS];              // Gram matrix
__device__ __nv_bfloat16 g_xhi[NWIN * NB * ND];     // normalized windows, hi plane
__device__ __nv_bfloat16 g_xlo[NWIN * NB * ND];     // lo plane
__device__ __nv_bfloat16 g_bThi[NBASIS * ND];       // basis^T [n][j], hi plane
__device__ __nv_bfloat16 g_bTlo[NBASIS * ND];       // lo plane
__device__ float g_sx2[NWIN * NB];                  // per-(win,b) sum x^2

// ---------------- dynamic SMEM byte offsets --------------------------------
// Phase B: rows padded to 264 bf16 = 528 B (ldsm stride mod 128 = 16, clean).
#define ROWB    528
#define A_T(p,pl) ((p) * 33792 + (pl) * 16896)   // coef [32][256] bf16, parity x plane
#define B_T(pl)   (67584 + (pl) * 67584)         // G_own [128][256] bf16, plane
#define SRED_B    202752                         // 48 floats
#define SEX_B     202944                         // 16 floats
#define SMEM_BYTES 203264
// Phase A (overlaps the regions above; strictly before G/A_T fill):
#define ROWX    2064                             // x row: 1024 bf16 + 16B pad
#define XP(pl)  ((pl) * 66048)                   // x planes [32][1024]
#define ROWSB   272                              // bT slab row: 128 bf16 + 16B pad
#define BSL(pl) (132096 + (pl) * 34816)          // bT slab [128][128], ends 201728

// ---------------------------------------------------------------------------
// Prep 1: normalized windows -> bf16 hi/lo planes + exact sumx2 partials.
// grid (32 b, 63 win), 256 threads.
// ---------------------------------------------------------------------------
__global__ void prep_windows(const float* __restrict__ spec) {
    int b = blockIdx.x, wn = blockIdx.y;
    int t = threadIdx.x;

    float v[4];
    float mn = 3.402823466e38f, mx = -3.402823466e38f;
#pragma unroll
    for (int r = 0; r < 4; r++) {
        int idx = t + 256 * r;
        int f = idx >> 3, tt = idx & 7;
        float val = spec[(b * 128 + f) * 256 + wn * 4 + tt];
        v[r] = val;
        mn = fminf(mn, val);
        mx = fmaxf(mx, val);
    }
#pragma unroll
    for (int o = 16; o > 0; o >>= 1) {
        mn = fminf(mn, __shfl_xor_sync(0xffffffffu, mn, o));
        mx = fmaxf(mx, __shfl_xor_sync(0xffffffffu, mx, o));
    }
    __shared__ float smn[8], smx[8], ss2[8];
    if ((t & 31) == 0) { smn[t >> 5] = mn; smx[t >> 5] = mx; }
    __syncthreads();
    float bmn = smn[0], bmx = smx[0];
#pragma unroll
    for (int i = 1; i < 8; i++) { bmn = fminf(bmn, smn[i]); bmx = fmaxf(bmx, smx[i]); }
    float d = bmx - bmn;

    __nv_bfloat16* dh = g_xhi + (wn * NB + b) * ND;
    __nv_bfloat16* dl = g_xlo + (wn * NB + b) * ND;
    float s2 = 0.f;
#pragma unroll
    for (int r = 0; r < 4; r++) {
        int idx = t + 256 * r;
        float nv = (v[r] - bmn) / d;
        __nv_bfloat16 hi = __float2bfloat16(nv);
        __nv_bfloat16 lo = __float2bfloat16(nv - __bfloat162float(hi));
        dh[idx] = hi;
        dl[idx] = lo;
        s2 = fmaf(nv, nv, s2);
    }
#pragma unroll
    for (int o = 16; o > 0; o >>= 1)
        s2 += __shfl_xor_sync(0xffffffffu, s2, o);
    if ((t & 31) == 0) ss2[t >> 5] = s2;
    __syncthreads();
    if (t == 0) {
        float a = 0.f;
#pragma unroll
        for (int i = 0; i < 8; i++) a += ss2[i];
        g_sx2[wn * NB + b] = a;
    }
}

// ---------------------------------------------------------------------------
// Prep 2: G = basis^T @ basis.  grid (8,8), 256 threads; 32x32 output tile.
// ---------------------------------------------------------------------------
__global__ void prep_G(const float* __restrict__ basis) {
    __shared__ float A[32][33], Bs[32][33];
    int k1b = blockIdx.y * 32, k2b = blockIdx.x * 32;
    int tx = threadIdx.x & 31, ty = threadIdx.x >> 5;
    float acc[4] = {0.f, 0.f, 0.f, 0.f};
    for (int j0 = 0; j0 < ND; j0 += 32) {
        __syncthreads();
#pragma unroll
        for (int s = 0; s < 4; s++) {
            A[ty + 8 * s][tx]  = basis[(j0 + ty + 8 * s) * NBASIS + k1b + tx];
            Bs[ty + 8 * s][tx] = basis[(j0 + ty + 8 * s) * NBASIS + k2b + tx];
        }
        __syncthreads();
#pragma unroll
        for (int jj = 0; jj < 32; jj++) {
            float bv = Bs[jj][tx];
            acc[0] = fmaf(A[jj][ty],      bv, acc[0]);
            acc[1] = fmaf(A[jj][ty + 8],  bv, acc[1]);
            acc[2] = fmaf(A[jj][ty + 16], bv, acc[2]);
            acc[3] = fmaf(A[jj][ty + 24], bv, acc[3]);
        }
    }
#pragma unroll
    for (int s = 0; s < 4; s++)
        g_G[(k1b + ty + 8 * s) * NBASIS + k2b + tx] = acc[s];
}

// ---------------------------------------------------------------------------
// Prep 3: bT[n][j] = bf16split(basis[j][n]).  grid (8 nt, 32 jt), block 32x32.
// ---------------------------------------------------------------------------
__global__ void prep_bT(const float* __restrict__ basis) {
    __shared__ float tile[32][33];
    int nbt = blockIdx.x * 32, jb = blockIdx.y * 32;
    int tx = threadIdx.x, ty = threadIdx.y;
    tile[ty][tx] = basis[(jb + ty) * NBASIS + nbt + tx];
    __syncthreads();
    float v = tile[tx][ty];    // = basis[jb+tx][nbt+ty]
    __nv_bfloat16 hi = __float2bfloat16(v);
    __nv_bfloat16 lo = __float2bfloat16(v - __bfloat162float(hi));
    g_bThi[(nbt + ty) * ND + jb + tx] = hi;
    g_bTlo[(nbt + ty) * ND + jb + tx] = lo;
}

// ---------------------------------------------------------------------------
// helpers
// ---------------------------------------------------------------------------
__device__ __forceinline__ uint32_t smem_u32(const void* p) {
    uint32_t a;
    asm("{ .reg .u64 t; cvta.to.shared.u64 t, %1; cvt.u32.u64 %0, t; }"
        : "=r"(a) : "l"(p));
    return a;
}
__device__ __forceinline__ uint32_t mapa_peer(uint32_t laddr, int peer) {
    uint32_t r;
    asm("mapa.shared::cluster.u32 %0, %1, %2;" : "=r"(r) : "r"(laddr), "r"(peer));
    return r;
}
__device__ __forceinline__ void dst_f32(uint32_t raddr, float a) {
    asm volatile("st.shared::cluster.b32 [%0], %1;"
                 :: "r"(raddr), "r"(__float_as_uint(a)) : "memory");
}
__device__ __forceinline__ void dst_u32(uint32_t raddr, uint32_t a) {
    asm volatile("st.shared::cluster.b32 [%0], %1;"
                 :: "r"(raddr), "r"(a) : "memory");
}
__device__ __forceinline__ void cluster_sync() {
    asm volatile("barrier.cluster.arrive.aligned;" ::: "memory");
    asm volatile("barrier.cluster.wait.aligned;" ::: "memory");
}
__device__ __forceinline__ void ldsm4(uint32_t& r0, uint32_t& r1,
                                      uint32_t& r2, uint32_t& r3, uint32_t addr) {
    asm volatile("ldmatrix.sync.aligned.m8n8.x4.shared.b16 {%0,%1,%2,%3}, [%4];"
                 : "=r"(r0), "=r"(r1), "=r"(r2), "=r"(r3) : "r"(addr));
}
__device__ __forceinline__ void mma16816(float& c0, float& c1, float& c2, float& c3,
                                         uint32_t a0, uint32_t a1, uint32_t a2,
                                         uint32_t a3, uint32_t b0, uint32_t b1) {
    asm volatile(
        "mma.sync.aligned.m16n8k16.row.col.f32.bf16.bf16.f32 "
        "{%0,%1,%2,%3}, {%4,%5,%6,%7}, {%8,%9}, {%0,%1,%2,%3};"
        : "+f"(c0), "+f"(c1), "+f"(c2), "+f"(c3)
        : "r"(a0), "r"(a1), "r"(a2), "r"(a3), "r"(b0), "r"(b1));
}
__device__ __forceinline__ unsigned short bfraw(__nv_bfloat16 h) {
    return *reinterpret_cast<unsigned short*>(&h);
}

// ---------------------------------------------------------------------------
// Main solver: 2-CTA cluster per window, 512 threads. rank owns k-half.
// Both GEMMs use mma.sync m16n8k16 bf16 3-pass split with the SAME fragment
// mapping: warp w -> mtile mb=(w&1)*16 (b), ntile nb=(w>>1)*16 (k_own);
// owned elem (t,e): b = mb+(l>>2)+(e>>1)*8, n = nb+t*8+(l&3)*2+(e&1).
// ---------------------------------------------------------------------------
__global__ __launch_bounds__(512, 1) __cluster_dims__(2, 1, 1)
void sc_solve(const int* __restrict__ n_iter_p, float* __restrict__ out) {
    extern __shared__ float smem[];
    char* smem8 = (char*)smem;
    float* sredf = (float*)(smem8 + SRED_B);
    float* sexf  = (float*)(smem8 + SEX_B);

    const int win  = blockIdx.x >> 1;
    const int rank = blockIdx.x & 1;
    const int tid = threadIdx.x;
    const int w = tid >> 5, l = tid & 31;
    const int n_iter = n_iter_p[0];

    const uint32_t sbase = smem_u32(smem);
    const uint32_t rbase = mapa_peer(sbase, 1 - rank);

    const int mb = (w & 1) * 16;       // b tile base
    const int nb = (w >> 1) * 16;      // k_own tile base

    // =================== Phase A: h = x @ basis[:,own] via mma ==============
    // copy x planes [32][1024] bf16 -> smem (ROWX-padded rows)
    {
        const uint4* xh4 = (const uint4*)(g_xhi + (size_t)win * NB * ND);
        const uint4* xl4 = (const uint4*)(g_xlo + (size_t)win * NB * ND);
#pragma unroll
        for (int c = tid; c < 4096; c += 512) {
            int row = c >> 7, col = c & 127;
            *(uint4*)(smem8 + XP(0) + row * ROWX + col * 16) = xh4[c];
            *(uint4*)(smem8 + XP(1) + row * ROWX + col * 16) = xl4[c];
        }
    }

    float hacc[8];
#pragma unroll
    for (int i = 0; i < 8; i++) hacc[i] = 0.f;

    const uint32_t axh = sbase + XP(0) + (uint32_t)(mb + (l & 15)) * ROWX + (l >> 4) * 16;
    const uint32_t axl = sbase + XP(1) + (uint32_t)(mb + (l & 15)) * ROWX + (l >> 4) * 16;
    const uint32_t sbh = sbase + BSL(0)
                       + (uint32_t)(nb + (l & 7) + (l >> 4) * 8) * ROWSB
                       + ((l >> 3) & 1) * 16;
    const uint32_t sbl = sbase + BSL(1)
                       + (uint32_t)(nb + (l & 7) + (l >> 4) * 8) * ROWSB
                       + ((l >> 3) & 1) * 16;

    for (int s = 0; s < 8; s++) {
        __syncthreads();   // x copy done (s=0) / prev slab reads done
        {   // copy bT slab [128 n][128 j] both planes
            const char* gh = (const char*)g_bThi + ((size_t)rank * KHALF * ND + s * 128) * 2;
            const char* gl = (const char*)g_bTlo + ((size_t)rank * KHALF * ND + s * 128) * 2;
#pragma unroll
            for (int c = tid; c < 2048; c += 512) {
                int n = c >> 4, ch = c & 15;
                *(uint4*)(smem8 + BSL(0) + n * ROWSB + ch * 16) =
                    *(const uint4*)(gh + (size_t)n * 2048 + ch * 16);
                *(uint4*)(smem8 + BSL(1) + n * ROWSB + ch * 16) =
                    *(const uint4*)(gl + (size_t)n * 2048 + ch * 16);
            }
        }
        __syncthreads();
#pragma unroll
        for (int kc = 0; kc < 8; kc++) {
            const uint32_t ka = (uint32_t)s * 256 + kc * 32;   // byte offset in x row
            const uint32_t kb = (uint32_t)kc * 32;             // byte offset in slab row
            uint32_t ah0, ah1, ah2, ah3, al0, al1, al2, al3;
            uint32_t bh0, bh1, bh2, bh3, bl0, bl1, bl2, bl3;
            ldsm4(ah0, ah1, ah2, ah3, axh + ka);
            ldsm4(bh0, bh1, bh2, bh3, sbh + kb);
            ldsm4(al0, al1, al2, al3, axl + ka);
            ldsm4(bl0, bl1, bl2, bl3, sbl + kb);
            mma16816(hacc[0], hacc[1], hacc[2], hacc[3], ah0, ah1, ah2, ah3, bh0, bh1);
            mma16816(hacc[4], hacc[5], hacc[6], hacc[7], ah0, ah1, ah2, ah3, bh2, bh3);
            mma16816(hacc[0], hacc[1], hacc[2], hacc[3], ah0, ah1, ah2, ah3, bl0, bl1);
            mma16816(hacc[4], hacc[5], hacc[6], hacc[7], ah0, ah1, ah2, ah3, bl2, bl3);
            mma16816(hacc[0], hacc[1], hacc[2], hacc[3], al0, al1, al2, al3, bh0, bh1);
            mma16816(hacc[4], hacc[5], hacc[6], hacc[7], al0, al1, al2, al3, bh2, bh3);
        }
    }
    __syncthreads();   // Phase A smem reads done

    float hreg[8];
#pragma unroll
    for (int i = 0; i < 8; i++) hreg[i] = hacc[i];

    // sumx2 from exact fp32 partials (fixed order -> identical on both ranks)
    float sumx2 = 0.f;
    {
        const float* sx = g_sx2 + win * NB;
#pragma unroll
        for (int i = 0; i < 32; i++) sumx2 += sx[i];
    }

    // =================== Phase B setup ======================================
    float coef[8], m[8], vv[8];
    uint32_t pairoff[4];
#pragma unroll
    for (int t = 0; t < 2; t++)
#pragma unroll
        for (int e = 0; e < 4; e++) {
            coef[t * 4 + e] = C0;
            m[t * 4 + e] = 0.f; vv[t * 4 + e] = 0.f;
            if ((e & 1) == 0) {
                int b = mb + (l >> 2) + (e >> 1) * 8;
                int n = nb + t * 8 + (l & 3) * 2;
                pairoff[t * 2 + (e >> 1)] =
                    (uint32_t)b * ROWB + (uint32_t)(rank * KHALF + n) * 2;
            }
        }

    // fill B planes: G_own rows (static), and A parity0 = split(C0)
    for (int idx = tid; idx < 128 * 256; idx += 512) {
        int n = idx >> 8, k = idx & 255;
        float gv = g_G[(rank * KHALF + n) * NBASIS + k];
        __nv_bfloat16 hi = __float2bfloat16(gv);
        __nv_bfloat16 lo = __float2bfloat16(gv - __bfloat162float(hi));
        uint32_t o = (uint32_t)n * ROWB + (uint32_t)k * 2;
        *(__nv_bfloat16*)(smem8 + B_T(0) + o) = hi;
        *(__nv_bfloat16*)(smem8 + B_T(1) + o) = lo;
    }
    {
        __nv_bfloat16 hi0 = __float2bfloat16(C0);
        __nv_bfloat16 lo0 = __float2bfloat16(C0 - __bfloat162float(hi0));
        for (int idx = tid; idx < 32 * 256; idx += 512) {
            int b = idx >> 8, k = idx & 255;
            uint32_t o = (uint32_t)b * ROWB + (uint32_t)k * 2;
            *(__nv_bfloat16*)(smem8 + A_T(0, 0) + o) = hi0;
            *(__nv_bfloat16*)(smem8 + A_T(0, 1) + o) = lo0;
        }
    }
    __syncthreads();
    cluster_sync();

    const uint32_t aoff = (uint32_t)(mb + (l & 15)) * ROWB + (uint32_t)((l >> 4) * 8) * 2;
    const uint32_t boff = (uint32_t)(nb + (l & 7) + (l >> 4) * 8) * ROWB
                        + (uint32_t)(((l >> 3) & 1) * 8) * 2;
    const uint32_t bhiB = sbase + B_T(0) + boff;
    const uint32_t bloB = sbase + B_T(1) + boff;

    float b1t = 1.f, b2t = 1.f;
    float old_loss = 1e-10f;

    for (int it = 0; it < n_iter; ++it) {
        const int p = it & 1;
        const uint32_t ahiB = sbase + A_T(p, 0) + aoff;
        const uint32_t aloB = sbase + A_T(p, 1) + aoff;

        // ---- GEMM: 3-pass bf16-split, fp32 accum ----
        float c0[4] = {0.f, 0.f, 0.f, 0.f};
        float c1[4] = {0.f, 0.f, 0.f, 0.f};
#pragma unroll 4
        for (int kc = 0; kc < 16; kc++) {
            const uint32_t kb = (uint32_t)kc * 32;
            uint32_t ah0, ah1, ah2, ah3, al0, al1, al2, al3;
            uint32_t bh0, bh1, bh2, bh3, bl0, bl1, bl2, bl3;
            ldsm4(ah0, ah1, ah2, ah3, ahiB + kb);
            ldsm4(bh0, bh1, bh2, bh3, bhiB + kb);
            ldsm4(al0, al1, al2, al3, aloB + kb);
            ldsm4(bl0, bl1, bl2, bl3, bloB + kb);
            mma16816(c0[0], c0[1], c0[2], c0[3], ah0, ah1, ah2, ah3, bh0, bh1);
            mma16816(c1[0], c1[1], c1[2], c1[3], ah0, ah1, ah2, ah3, bh2, bh3);
            mma16816(c0[0], c0[1], c0[2], c0[3], ah0, ah1, ah2, ah3, bl0, bl1);
            mma16816(c1[0], c1[1], c1[2], c1[3], ah0, ah1, ah2, ah3, bl2, bl3);
            mma16816(c0[0], c0[1], c0[2], c0[3], al0, al1, al2, al3, bh0, bh1);
            mma16816(c1[0], c1[1], c1[2], c1[3], al0, al1, al2, al3, bh2, bh3);
        }
        float cg[8];
#pragma unroll
        for (int e = 0; e < 4; e++) { cg[e] = c0[e]; cg[4 + e] = c1[e]; }

        // ---- loss partials over owned 8 elements ----
        float pcg = 0.f, pch = 0.f, pl1 = 0.f;
#pragma unroll
        for (int i = 0; i < 8; i++) {
            pcg = fmaf(cg[i], coef[i], pcg);
            pch = fmaf(coef[i], hreg[i], pch);
            pl1 += fabsf(coef[i]);
        }
#pragma unroll
        for (int o = 16; o > 0; o >>= 1) {
            pcg += __shfl_xor_sync(0xffffffffu, pcg, o);
            pch += __shfl_xor_sync(0xffffffffu, pch, o);
            pl1 += __shfl_xor_sync(0xffffffffu, pl1, o);
        }
        if (l == 0) { sredf[w] = pcg; sredf[16 + w] = pch; sredf[32 + w] = pl1; }
        __syncthreads();   // GEMM A reads done; sred published

        if (tid == 0) {
            float a = 0.f, b = 0.f, c = 0.f;
#pragma unroll
            for (int i = 0; i < 16; i++) {
                a += sredf[i]; b += sredf[16 + i]; c += sredf[32 + i];
            }
            const int fo = p * 8 + rank * 4;
            sexf[fo + 0] = a; sexf[fo + 1] = b; sexf[fo + 2] = c;
            dst_f32(rbase + SEX_B + (fo + 0) * 4, a);
            dst_f32(rbase + SEX_B + (fo + 1) * 4, b);
            dst_f32(rbase + SEX_B + (fo + 2) * 4, c);
        }

        // ---- Adam on owned 8 ----
        b1t *= B1C;
        b2t *= B2C;
        const float gs = 2.0f / 32768.0f;
        const float rb1 = 1.0f / (1.0f - b1t);
        const float rb2 = 1.0f / (1.0f - b2t);
#pragma unroll
        for (int i = 0; i < 8; i++) {
            float c = coef[i];
            float sg = (c > 0.f) ? 1.f : ((c < 0.f) ? -1.f : 0.f);
            float grad = (cg[i] - hreg[i]) * gs + (LAMC / 8192.0f) * sg;
            m[i]  = B1C * m[i] + (1.0f - B1C) * grad;
            vv[i] = B2C * vv[i] + (1.0f - B2C) * grad * grad;
            coef[i] = c - LRC * (m[i] * rb1) / (sqrtf(vv[i] * rb2) + EPSC);
        }
        // write bf16 split pairs into A parity^1 (local + peer)
        const uint32_t lAh = A_T(p ^ 1, 0), lAl = A_T(p ^ 1, 1);
#pragma unroll
        for (int t = 0; t < 2; t++)
#pragma unroll
            for (int rs = 0; rs < 2; rs++) {
                const int i0 = t * 4 + rs * 2;
                __nv_bfloat16 h0 = __float2bfloat16(coef[i0]);
                __nv_bfloat16 h1 = __float2bfloat16(coef[i0 + 1]);
                __nv_bfloat16 l0 = __float2bfloat16(coef[i0] - __bfloat162float(h0));
                __nv_bfloat16 l1 = __float2bfloat16(coef[i0 + 1] - __bfloat162float(h1));
                uint32_t hp = (uint32_t)bfraw(h0) | ((uint32_t)bfraw(h1) << 16);
                uint32_t lp = (uint32_t)bfraw(l0) | ((uint32_t)bfraw(l1) << 16);
                const uint32_t o = pairoff[t * 2 + rs];
                *(uint32_t*)(smem8 + lAh + o) = hp;
                *(uint32_t*)(smem8 + lAl + o) = lp;
                dst_u32(rbase + lAh + o, hp);
                dst_u32(rbase + lAl + o, lp);
            }

        cluster_sync();   // publishes A parity^1 + loss partials

        // ---- loss (identical on both ranks) ----
        const float Scg = sexf[p * 8 + 0] + sexf[p * 8 + 4];
        const float Sch = sexf[p * 8 + 1] + sexf[p * 8 + 5];
        const float Sl1 = sexf[p * 8 + 2] + sexf[p * 8 + 6];
        const float mse  = (Scg - 2.0f * Sch + sumx2) * (1.0f / 32768.0f);
        const float loss = mse + LAMC * (Sl1 * (1.0f / 8192.0f));

        const float conv_m = fabsf(old_loss - loss) / old_loss;
        old_loss = loss;
        if (conv_m < TOLC) break;   // uniform across cluster
    }

    // =================== output: out[b][kg][win] from registers =============
#pragma unroll
    for (int t = 0; t < 2; t++)
#pragma unroll
        for (int e = 0; e < 4; e++) {
            int b = mb + (l >> 2) + (e >> 1) * 8;
            int kg = rank * KHALF + nb + t * 8 + (l & 3) * 2 + (e & 1);
            out[(b * NBASIS + kg) * NWIN + win] = coef[t * 4 + e];
        }
}

// ---------------------------------------------------------------------------
extern "C" void kernel_launch(void* const* d_in, const int* in_sizes, int n_in,
                              void* d_out, int out_size) {
    const float* spec  = (const float*)d_in[0];
    const float* basis = (const float*)d_in[1];
    const int* n_iter  = (const int*)d_in[2];
    float* out = (float*)d_out;

    prep_windows<<<dim3(NB, NWIN), 256>>>(spec);
    prep_G<<<dim3(8, 8), 256>>>(basis);
    prep_bT<<<dim3(8, 32), dim3(32, 32)>>>(basis);

    cudaFuncSetAttribute(sc_solve, cudaFuncAttributeMaxDynamicSharedMemorySize,
                         SMEM_BYTES);
    sc_solve<<<2 * NWIN, 512, SMEM_BYTES>>>(n_iter, out);
}

// round 17
// speedup vs baseline: 19.6516x; 1.0304x over previous
#include <cuda_runtime.h>
#include <cuda_bf16.h>
#include <stdint.h>
#include <math.h>

#define NWIN   63
#define NB     32
#define ND     1024
#define NBASIS 256
#define KHALF  128
#define LAMC   0.2f
#define LRC    0.001f
#define B1C    0.9f
#define B2C    0.999f
#define EPSC   1e-8f
#define TOLC   1e-3f
#define C0     (0.5f / 256.0f)

// scratch (allowed: __device__ globals, no runtime alloc)
__device__ float g_G[NBASIS * NBASIS];              // Gram matrix
__device__ __nv_bfloat16 g_xhi[NWIN * NB * ND];     // normalized windows, hi plane
__device__ __nv_bfloat16 g_xlo[NWIN * NB * ND];     // lo plane
__device__ __nv_bfloat16 g_bThi[NBASIS * ND];       // basis^T [n][j], hi plane
__device__ __nv_bfloat16 g_bTlo[NBASIS * ND];       // lo plane
__device__ float g_sx2[NWIN * NB];                  // per-(win,b) sum x^2

// ---------------- dynamic SMEM byte offsets --------------------------------
// Phase B: rows padded to 264 bf16 = 528 B (ldsm stride mod 128 = 16, clean).
#define ROWB    528
#define A_T(p,pl) ((p) * 33792 + (pl) * 16896)   // coef [32][256] bf16, parity x plane
#define B_T(pl)   (67584 + (pl) * 67584)         // G_own [128][256] bf16, plane
#define SRED_B    202752                         // 48 floats
#define SEX_B     202944                         // 16 floats
#define SMEM_BYTES 203264
// Phase A (overlaps the regions above; strictly before G/A_T fill):
#define ROWX    2064                             // x row: 1024 bf16 + 16B pad
#define XP(pl)  ((pl) * 66048)                   // x planes [32][1024]
#define ROWSB   272                              // bT slab row: 128 bf16 + 16B pad
#define BSL(pl) (132096 + (pl) * 34816)          // bT slab [128][128], ends 201728

// ---------------------------------------------------------------------------
// Prep 1: normalized windows -> bf16 hi/lo planes + exact sumx2 partials.
// grid (32 b, 63 win), 256 threads.
// ---------------------------------------------------------------------------
__global__ void prep_windows(const float* __restrict__ spec) {
    int b = blockIdx.x, wn = blockIdx.y;
    int t = threadIdx.x;

    float v[4];
    float mn = 3.402823466e38f, mx = -3.402823466e38f;
#pragma unroll
    for (int r = 0; r < 4; r++) {
        int idx = t + 256 * r;
        int f = idx >> 3, tt = idx & 7;
        float val = spec[(b * 128 + f) * 256 + wn * 4 + tt];
        v[r] = val;
        mn = fminf(mn, val);
        mx = fmaxf(mx, val);
    }
#pragma unroll
    for (int o = 16; o > 0; o >>= 1) {
        mn = fminf(mn, __shfl_xor_sync(0xffffffffu, mn, o));
        mx = fmaxf(mx, __shfl_xor_sync(0xffffffffu, mx, o));
    }
    __shared__ float smn[8], smx[8], ss2[8];
    if ((t & 31) == 0) { smn[t >> 5] = mn; smx[t >> 5] = mx; }
    __syncthreads();
    float bmn = smn[0], bmx = smx[0];
#pragma unroll
    for (int i = 1; i < 8; i++) { bmn = fminf(bmn, smn[i]); bmx = fmaxf(bmx, smx[i]); }
    float d = bmx - bmn;

    __nv_bfloat16* dh = g_xhi + (wn * NB + b) * ND;
    __nv_bfloat16* dl = g_xlo + (wn * NB + b) * ND;
    float s2 = 0.f;
#pragma unroll
    for (int r = 0; r < 4; r++) {
        int idx = t + 256 * r;
        float nv = (v[r] - bmn) / d;
        __nv_bfloat16 hi = __float2bfloat16(nv);
        __nv_bfloat16 lo = __float2bfloat16(nv - __bfloat162float(hi));
        dh[idx] = hi;
        dl[idx] = lo;
        s2 = fmaf(nv, nv, s2);
    }
#pragma unroll
    for (int o = 16; o > 0; o >>= 1)
        s2 += __shfl_xor_sync(0xffffffffu, s2, o);
    if ((t & 31) == 0) ss2[t >> 5] = s2;
    __syncthreads();
    if (t == 0) {
        float a = 0.f;
#pragma unroll
        for (int i = 0; i < 8; i++) a += ss2[i];
        g_sx2[wn * NB + b] = a;
    }
}

// ---------------------------------------------------------------------------
// Prep 2: G = basis^T @ basis.  grid (8,8), 256 threads; 32x32 output tile.
// ---------------------------------------------------------------------------
__global__ void prep_G(const float* __restrict__ basis) {
    __shared__ float A[32][33], Bs[32][33];
    int k1b = blockIdx.y * 32, k2b = blockIdx.x * 32;
    int tx = threadIdx.x & 31, ty = threadIdx.x >> 5;
    float acc[4] = {0.f, 0.f, 0.f, 0.f};
    for (int j0 = 0; j0 < ND; j0 += 32) {
        __syncthreads();
#pragma unroll
        for (int s = 0; s < 4; s++) {
            A[ty + 8 * s][tx]  = basis[(j0 + ty + 8 * s) * NBASIS + k1b + tx];
            Bs[ty + 8 * s][tx] = basis[(j0 + ty + 8 * s) * NBASIS + k2b + tx];
        }
        __syncthreads();
#pragma unroll
        for (int jj = 0; jj < 32; jj++) {
            float bv = Bs[jj][tx];
            acc[0] = fmaf(A[jj][ty],      bv, acc[0]);
            acc[1] = fmaf(A[jj][ty + 8],  bv, acc[1]);
            acc[2] = fmaf(A[jj][ty + 16], bv, acc[2]);
            acc[3] = fmaf(A[jj][ty + 24], bv, acc[3]);
        }
    }
#pragma unroll
    for (int s = 0; s < 4; s++)
        g_G[(k1b + ty + 8 * s) * NBASIS + k2b + tx] = acc[s];
}

// ---------------------------------------------------------------------------
// Prep 3: bT[n][j] = bf16split(basis[j][n]).  grid (8 nt, 32 jt), block 32x32.
// ---------------------------------------------------------------------------
__global__ void prep_bT(const float* __restrict__ basis) {
    __shared__ float tile[32][33];
    int nbt = blockIdx.x * 32, jb = blockIdx.y * 32;
    int tx = threadIdx.x, ty = threadIdx.y;
    tile[ty][tx] = basis[(jb + ty) * NBASIS + nbt + tx];
    __syncthreads();
    float v = tile[tx][ty];    // = basis[jb+tx][nbt+ty]
    __nv_bfloat16 hi = __float2bfloat16(v);
    __nv_bfloat16 lo = __float2bfloat16(v - __bfloat162float(hi));
    g_bThi[(nbt + ty) * ND + jb + tx] = hi;
    g_bTlo[(nbt + ty) * ND + jb + tx] = lo;
}

// ---------------------------------------------------------------------------
// helpers
// ---------------------------------------------------------------------------
__device__ __forceinline__ uint32_t smem_u32(const void* p) {
    uint32_t a;
    asm("{ .reg .u64 t; cvta.to.shared.u64 t, %1; cvt.u32.u64 %0, t; }"
        : "=r"(a) : "l"(p));
    return a;
}
__device__ __forceinline__ uint32_t mapa_peer(uint32_t laddr, int peer) {
    uint32_t r;
    asm("mapa.shared::cluster.u32 %0, %1, %2;" : "=r"(r) : "r"(laddr), "r"(peer));
    return r;
}
__device__ __forceinline__ void dst_f32(uint32_t raddr, float a) {
    asm volatile("st.shared::cluster.b32 [%0], %1;"
                 :: "r"(raddr), "r"(__float_as_uint(a)) : "memory");
}
__device__ __forceinline__ void dst_u32(uint32_t raddr, uint32_t a) {
    asm volatile("st.shared::cluster.b32 [%0], %1;"
                 :: "r"(raddr), "r"(a) : "memory");
}
__device__ __forceinline__ void cluster_sync() {
    asm volatile("barrier.cluster.arrive.aligned;" ::: "memory");
    asm volatile("barrier.cluster.wait.aligned;" ::: "memory");
}
__device__ __forceinline__ void cluster_arrive() {
    asm volatile("barrier.cluster.arrive.aligned;" ::: "memory");
}
__device__ __forceinline__ void cluster_wait() {
    asm volatile("barrier.cluster.wait.aligned;" ::: "memory");
}
__device__ __forceinline__ void ldsm4(uint32_t& r0, uint32_t& r1,
                                      uint32_t& r2, uint32_t& r3, uint32_t addr) {
    asm volatile("ldmatrix.sync.aligned.m8n8.x4.shared.b16 {%0,%1,%2,%3}, [%4];"
                 : "=r"(r0), "=r"(r1), "=r"(r2), "=r"(r3) : "r"(addr));
}
__device__ __forceinline__ void mma16816(float& c0, float& c1, float& c2, float& c3,
                                         uint32_t a0, uint32_t a1, uint32_t a2,
                                         uint32_t a3, uint32_t b0, uint32_t b1) {
    asm volatile(
        "mma.sync.aligned.m16n8k16.row.col.f32.bf16.bf16.f32 "
        "{%0,%1,%2,%3}, {%4,%5,%6,%7}, {%8,%9}, {%0,%1,%2,%3};"
        : "+f"(c0), "+f"(c1), "+f"(c2), "+f"(c3)
        : "r"(a0), "r"(a1), "r"(a2), "r"(a3), "r"(b0), "r"(b1));
}
__device__ __forceinline__ unsigned short bfraw(__nv_bfloat16 h) {
    return *reinterpret_cast<unsigned short*>(&h);
}

// ---------------------------------------------------------------------------
// Main solver: 2-CTA cluster per window, 512 threads. rank owns k-half.
// Both GEMMs use mma.sync m16n8k16 bf16 3-pass split with the SAME fragment
// mapping: warp w -> mtile mb=(w&1)*16 (b), ntile nb=(w>>1)*16 (k_own);
// owned elem (t,e): b = mb+(l>>2)+(e>>1)*8, n = nb+t*8+(l&3)*2+(e&1).
// Convergence check is DEFERRED one iteration (identical applied-update set),
// so the loss reduction/exchange hides behind the next iteration's GEMM.
// ---------------------------------------------------------------------------
__global__ __launch_bounds__(512, 1) __cluster_dims__(2, 1, 1)
void sc_solve(const int* __restrict__ n_iter_p, float* __restrict__ out) {
    extern __shared__ float smem[];
    char* smem8 = (char*)smem;
    float* sredf = (float*)(smem8 + SRED_B);
    float* sexf  = (float*)(smem8 + SEX_B);

    const int win  = blockIdx.x >> 1;
    const int rank = blockIdx.x & 1;
    const int tid = threadIdx.x;
    const int w = tid >> 5, l = tid & 31;
    const int n_iter = n_iter_p[0];

    const uint32_t sbase = smem_u32(smem);
    const uint32_t rbase = mapa_peer(sbase, 1 - rank);

    const int mb = (w & 1) * 16;       // b tile base
    const int nb = (w >> 1) * 16;      // k_own tile base

    // =================== Phase A: h = x @ basis[:,own] via mma ==============
    {
        const uint4* xh4 = (const uint4*)(g_xhi + (size_t)win * NB * ND);
        const uint4* xl4 = (const uint4*)(g_xlo + (size_t)win * NB * ND);
#pragma unroll
        for (int c = tid; c < 4096; c += 512) {
            int row = c >> 7, col = c & 127;
            *(uint4*)(smem8 + XP(0) + row * ROWX + col * 16) = xh4[c];
            *(uint4*)(smem8 + XP(1) + row * ROWX + col * 16) = xl4[c];
        }
    }

    float hacc[8];
#pragma unroll
    for (int i = 0; i < 8; i++) hacc[i] = 0.f;

    const uint32_t axh = sbase + XP(0) + (uint32_t)(mb + (l & 15)) * ROWX + (l >> 4) * 16;
    const uint32_t axl = sbase + XP(1) + (uint32_t)(mb + (l & 15)) * ROWX + (l >> 4) * 16;
    const uint32_t sbh = sbase + BSL(0)
                       + (uint32_t)(nb + (l & 7) + (l >> 4) * 8) * ROWSB
                       + ((l >> 3) & 1) * 16;
    const uint32_t sbl = sbase + BSL(1)
                       + (uint32_t)(nb + (l & 7) + (l >> 4) * 8) * ROWSB
                       + ((l >> 3) & 1) * 16;

    for (int s = 0; s < 8; s++) {
        __syncthreads();   // x copy done (s=0) / prev slab reads done
        {   // copy bT slab [128 n][128 j] both planes
            const char* gh = (const char*)g_bThi + ((size_t)rank * KHALF * ND + s * 128) * 2;
            const char* gl = (const char*)g_bTlo + ((size_t)rank * KHALF * ND + s * 128) * 2;
#pragma unroll
            for (int c = tid; c < 2048; c += 512) {
                int n = c >> 4, ch = c & 15;
                *(uint4*)(smem8 + BSL(0) + n * ROWSB + ch * 16) =
                    *(const uint4*)(gh + (size_t)n * 2048 + ch * 16);
                *(uint4*)(smem8 + BSL(1) + n * ROWSB + ch * 16) =
                    *(const uint4*)(gl + (size_t)n * 2048 + ch * 16);
            }
        }
        __syncthreads();
#pragma unroll
        for (int kc = 0; kc < 8; kc++) {
            const uint32_t ka = (uint32_t)s * 256 + kc * 32;
            const uint32_t kb = (uint32_t)kc * 32;
            uint32_t ah0, ah1, ah2, ah3, al0, al1, al2, al3;
            uint32_t bh0, bh1, bh2, bh3, bl0, bl1, bl2, bl3;
            ldsm4(ah0, ah1, ah2, ah3, axh + ka);
            ldsm4(bh0, bh1, bh2, bh3, sbh + kb);
            ldsm4(al0, al1, al2, al3, axl + ka);
            ldsm4(bl0, bl1, bl2, bl3, sbl + kb);
            mma16816(hacc[0], hacc[1], hacc[2], hacc[3], ah0, ah1, ah2, ah3, bh0, bh1);
            mma16816(hacc[4], hacc[5], hacc[6], hacc[7], ah0, ah1, ah2, ah3, bh2, bh3);
            mma16816(hacc[0], hacc[1], hacc[2], hacc[3], ah0, ah1, ah2, ah3, bl0, bl1);
            mma16816(hacc[4], hacc[5], hacc[6], hacc[7], ah0, ah1, ah2, ah3, bl2, bl3);
            mma16816(hacc[0], hacc[1], hacc[2], hacc[3], al0, al1, al2, al3, bh0, bh1);
            mma16816(hacc[4], hacc[5], hacc[6], hacc[7], al0, al1, al2, al3, bh2, bh3);
        }
    }
    __syncthreads();   // Phase A smem reads done

    float hreg[8];
#pragma unroll
    for (int i = 0; i < 8; i++) hreg[i] = hacc[i];

    // sumx2 from exact fp32 partials (fixed order -> identical on both ranks)
    float sumx2 = 0.f;
    {
        const float* sx = g_sx2 + win * NB;
#pragma unroll
        for (int i = 0; i < 32; i++) sumx2 += sx[i];
    }

    // =================== Phase B setup ======================================
    float coef[8], m[8], vv[8];
    uint32_t pairoff[4];
#pragma unroll
    for (int t = 0; t < 2; t++)
#pragma unroll
        for (int e = 0; e < 4; e++) {
            coef[t * 4 + e] = C0;
            m[t * 4 + e] = 0.f; vv[t * 4 + e] = 0.f;
            if ((e & 1) == 0) {
                int b = mb + (l >> 2) + (e >> 1) * 8;
                int n = nb + t * 8 + (l & 3) * 2;
                pairoff[t * 2 + (e >> 1)] =
                    (uint32_t)b * ROWB + (uint32_t)(rank * KHALF + n) * 2;
            }
        }

    // fill B planes: G_own rows (static), and A parity0 = split(C0)
    for (int idx = tid; idx < 128 * 256; idx += 512) {
        int n = idx >> 8, k = idx & 255;
        float gv = g_G[(rank * KHALF + n) * NBASIS + k];
        __nv_bfloat16 hi = __float2bfloat16(gv);
        __nv_bfloat16 lo = __float2bfloat16(gv - __bfloat162float(hi));
        uint32_t o = (uint32_t)n * ROWB + (uint32_t)k * 2;
        *(__nv_bfloat16*)(smem8 + B_T(0) + o) = hi;
        *(__nv_bfloat16*)(smem8 + B_T(1) + o) = lo;
    }
    {
        __nv_bfloat16 hi0 = __float2bfloat16(C0);
        __nv_bfloat16 lo0 = __float2bfloat16(C0 - __bfloat162float(hi0));
        for (int idx = tid; idx < 32 * 256; idx += 512) {
            int b = idx >> 8, k = idx & 255;
            uint32_t o = (uint32_t)b * ROWB + (uint32_t)k * 2;
            *(__nv_bfloat16*)(smem8 + A_T(0, 0) + o) = hi0;
            *(__nv_bfloat16*)(smem8 + A_T(0, 1) + o) = lo0;
        }
    }
    __syncthreads();
    cluster_sync();     // peer setup done (its SMEM is safe to write remotely)
    cluster_arrive();   // arrive #0 for the wait at loop top, iteration 0

    const uint32_t aoff = (uint32_t)(mb + (l & 15)) * ROWB + (uint32_t)((l >> 4) * 8) * 2;
    const uint32_t boff = (uint32_t)(nb + (l & 7) + (l >> 4) * 8) * ROWB
                        + (uint32_t)(((l >> 3) & 1) * 8) * 2;
    const uint32_t bhiB = sbase + B_T(0) + boff;
    const uint32_t bloB = sbase + B_T(1) + boff;

    float b1t = 1.f, b2t = 1.f;
    float old_loss = 1e-10f;   // loss_{it-2} at check time

    for (int it = 0; it < n_iter; ++it) {
        const int p = it & 1;
        const uint32_t ahiB = sbase + A_T(p, 0) + aoff;
        const uint32_t aloB = sbase + A_T(p, 1) + aoff;

        cluster_wait();   // tiles parity p + loss slots (it-1) visible

        // ---- GEMM: 3-pass bf16-split, fp32 accum ----
        float c0[4] = {0.f, 0.f, 0.f, 0.f};
        float c1[4] = {0.f, 0.f, 0.f, 0.f};
#pragma unroll 4
        for (int kc = 0; kc < 16; kc++) {
            const uint32_t kb = (uint32_t)kc * 32;
            uint32_t ah0, ah1, ah2, ah3, al0, al1, al2, al3;
            uint32_t bh0, bh1, bh2, bh3, bl0, bl1, bl2, bl3;
            ldsm4(ah0, ah1, ah2, ah3, ahiB + kb);
            ldsm4(bh0, bh1, bh2, bh3, bhiB + kb);
            ldsm4(al0, al1, al2, al3, aloB + kb);
            ldsm4(bl0, bl1, bl2, bl3, bloB + kb);
            mma16816(c0[0], c0[1], c0[2], c0[3], ah0, ah1, ah2, ah3, bh0, bh1);
            mma16816(c1[0], c1[1], c1[2], c1[3], ah0, ah1, ah2, ah3, bh2, bh3);
            mma16816(c0[0], c0[1], c0[2], c0[3], ah0, ah1, ah2, ah3, bl0, bl1);
            mma16816(c1[0], c1[1], c1[2], c1[3], ah0, ah1, ah2, ah3, bl2, bl3);
            mma16816(c0[0], c0[1], c0[2], c0[3], al0, al1, al2, al3, bh0, bh1);
            mma16816(c1[0], c1[1], c1[2], c1[3], al0, al1, al2, al3, bh2, bh3);
        }
        float cg[8];
#pragma unroll
        for (int e = 0; e < 4; e++) { cg[e] = c0[e]; cg[4 + e] = c1[e]; }

        // ---- deferred convergence check: loss_{it-1} vs loss_{it-2} ----
        if (it > 0) {
            const int q = p ^ 1;
            const float Scg = sexf[q * 8 + 0] + sexf[q * 8 + 4];
            const float Sch = sexf[q * 8 + 1] + sexf[q * 8 + 5];
            const float Sl1 = sexf[q * 8 + 2] + sexf[q * 8 + 6];
            const float mse  = (Scg - 2.0f * Sch + sumx2) * (1.0f / 32768.0f);
            const float loss = mse + LAMC * (Sl1 * (1.0f / 8192.0f));
            const float conv_m = fabsf(old_loss - loss) / old_loss;
            old_loss = loss;
            if (conv_m < TOLC) break;   // uniform across cluster; skip update_it
        }

        // ---- loss partials over owned 8 elements (pre-update coef) ----
        float pcg = 0.f, pch = 0.f, pl1 = 0.f;
#pragma unroll
        for (int i = 0; i < 8; i++) {
            pcg = fmaf(cg[i], coef[i], pcg);
            pch = fmaf(coef[i], hreg[i], pch);
            pl1 += fabsf(coef[i]);
        }
#pragma unroll
        for (int o = 16; o > 0; o >>= 1) {
            pcg += __shfl_xor_sync(0xffffffffu, pcg, o);
            pch += __shfl_xor_sync(0xffffffffu, pch, o);
            pl1 += __shfl_xor_sync(0xffffffffu, pl1, o);
        }
        if (l == 0) { sredf[w] = pcg; sredf[16 + w] = pch; sredf[32 + w] = pl1; }
        __syncthreads();   // GEMM A reads done; sredf published

        // warps 0-2: parallel 16->1 sum of metric w; push slots parity p
        if (w < 3) {
            float v = (l < 16) ? sredf[w * 16 + l] : 0.f;
#pragma unroll
            for (int o = 16; o > 0; o >>= 1)
                v += __shfl_xor_sync(0xffffffffu, v, o);
            if (l == 0) {
                const int fo = p * 8 + rank * 4 + w;
                sexf[fo] = v;
                dst_f32(rbase + SEX_B + fo * 4, v);
            }
        }

        // ---- Adam on owned 8 ----
        b1t *= B1C;
        b2t *= B2C;
        const float gs = 2.0f / 32768.0f;
        const float rb1 = 1.0f / (1.0f - b1t);
        const float rb2 = 1.0f / (1.0f - b2t);
#pragma unroll
        for (int i = 0; i < 8; i++) {
            float c = coef[i];
            float sg = (c > 0.f) ? 1.f : ((c < 0.f) ? -1.f : 0.f);
            float grad = (cg[i] - hreg[i]) * gs + (LAMC / 8192.0f) * sg;
            m[i]  = B1C * m[i] + (1.0f - B1C) * grad;
            vv[i] = B2C * vv[i] + (1.0f - B2C) * grad * grad;
            float denom = sqrtf(vv[i] * rb2) + EPSC;
            coef[i] = c - __fdividef(LRC * (m[i] * rb1), denom);
        }
        // write bf16 split pairs into A parity^1 (local + peer)
        const uint32_t lAh = A_T(p ^ 1, 0), lAl = A_T(p ^ 1, 1);
#pragma unroll
        for (int t = 0; t < 2; t++)
#pragma unroll
            for (int rs = 0; rs < 2; rs++) {
                const int i0 = t * 4 + rs * 2;
                __nv_bfloat16 h0 = __float2bfloat16(coef[i0]);
                __nv_bfloat16 h1 = __float2bfloat16(coef[i0 + 1]);
                __nv_bfloat16 l0 = __float2bfloat16(coef[i0] - __bfloat162float(h0));
                __nv_bfloat16 l1 = __float2bfloat16(coef[i0 + 1] - __bfloat162float(h1));
                uint32_t hp = (uint32_t)bfraw(h0) | ((uint32_t)bfraw(h1) << 16);
                uint32_t lp = (uint32_t)bfraw(l0) | ((uint32_t)bfraw(l1) << 16);
                const uint32_t o = pairoff[t * 2 + rs];
                *(uint32_t*)(smem8 + lAh + o) = hp;
                *(uint32_t*)(smem8 + lAl + o) = lp;
                dst_u32(rbase + lAh + o, hp);
                dst_u32(rbase + lAl + o, lp);
            }

        __syncthreads();   // all threads' remote stores issued
        if (it + 1 < n_iter)
            cluster_arrive();   // release: publishes tiles parity^1 + slots p
    }

    // =================== output: out[b][kg][win] from registers =============
#pragma unroll
    for (int t = 0; t < 2; t++)
#pragma unroll
        for (int e = 0; e < 4; e++) {
            int b = mb + (l >> 2) + (e >> 1) * 8;
            int kg = rank * KHALF + nb + t * 8 + (l & 3) * 2 + (e & 1);
            out[(b * NBASIS + kg) * NWIN + win] = coef[t * 4 + e];
        }
}

// ---------------------------------------------------------------------------
extern "C" void kernel_launch(void* const* d_in, const int* in_sizes, int n_in,
                              void* d_out, int out_size) {
    const float* spec  = (const float*)d_in[0];
    const float* basis = (const float*)d_in[1];
    const int* n_iter  = (const int*)d_in[2];
    float* out = (float*)d_out;

    prep_windows<<<dim3(NB, NWIN), 256>>>(spec);
    prep_G<<<dim3(8, 8), 256>>>(basis);
    prep_bT<<<dim3(8, 32), dim3(32, 32)>>>(basis);

    cudaFuncSetAttribute(sc_solve, cudaFuncAttributeMaxDynamicSharedMemorySize,
                         SMEM_BYTES);
    sc_solve<<<2 * NWIN, 512, SMEM_BYTES>>>(n_iter, out);
}